// round 6
// baseline (speedup 1.0000x reference)
#include <cuda_runtime.h>
#include <cuda_bf16.h>

#define MAXN 170000
#define MAXE 1200000
#define DF   128
#define HEADS 4
#define NEG_SLOPE 0.2f

// -------- scratch (device globals; no allocations allowed) --------
__device__ __align__(16) float g_h[MAXN * DF];       // node projections h = x @ W_embed
__device__ __align__(16) float g_ds[MAXN * HEADS];   // dot_src
__device__ __align__(16) float g_dd[MAXN * HEADS];   // dot_dst
__device__ int g_cnt[MAXN];                          // per-dst edge counts
__device__ int g_off[MAXN + 1];                      // CSR offsets
__device__ int g_cur[MAXN];                          // scatter cursors
__device__ int g_ssrc[MAXE];                         // src indices sorted by dst

// ---------------- zero counts -------------------------------------
__global__ void zero_cnt_kernel(int N) {
    int i = blockIdx.x * blockDim.x + threadIdx.x;
    if (i < N) g_cnt[i] = 0;
}

// ---------------- histogram of dst --------------------------------
__global__ void hist_kernel(const int* __restrict__ dst, int E) {
    int e = blockIdx.x * blockDim.x + threadIdx.x;
    if (e < E) atomicAdd(&g_cnt[dst[e]], 1);
}

// ---------------- single-block chunked exclusive scan -------------
__global__ void scan_kernel(int N, int E) {
    __shared__ int sh[1024];
    int t = threadIdx.x;
    int chunk = (N + 1023) >> 10;
    int beg = t * chunk;
    int end = beg + chunk; if (end > N) end = N;

    int s = 0;
    for (int i = beg; i < end; i++) s += g_cnt[i];
    sh[t] = s;
    __syncthreads();
    for (int off = 1; off < 1024; off <<= 1) {
        int v = (t >= off) ? sh[t - off] : 0;
        __syncthreads();
        sh[t] += v;
        __syncthreads();
    }
    int run = sh[t] - s;   // exclusive prefix for this thread's chunk
    for (int i = beg; i < end; i++) {
        g_off[i] = run;
        g_cur[i] = run;
        run += g_cnt[i];
    }
    if (t == 1023) g_off[N] = E;
}

// ---------------- scatter src into dst-sorted order ---------------
__global__ void scatter_kernel(const int* __restrict__ src,
                               const int* __restrict__ dst, int E) {
    int e = blockIdx.x * blockDim.x + threadIdx.x;
    if (e < E) {
        int d = dst[e];
        int pos = atomicAdd(&g_cur[d], 1);
        g_ssrc[pos] = src[e];
    }
}

// ---------------- fused dual GEMM (128x128x8, 8x8 microtile) ------
// by==0: x @ W_embed -> g_h ; by==1: x @ W_lin (+bias) -> d_out
__global__ __launch_bounds__(256, 2)
void gemm_kernel(const float* __restrict__ x,
                 const float* __restrict__ W_embed,
                 const float* __restrict__ W_lin,
                 const float* __restrict__ bias,
                 float* __restrict__ lin_out,
                 int N)
{
    __shared__ __align__(16) float As[2][8][128];
    __shared__ __align__(16) float Bs[2][8][128];

    int by = blockIdx.y;
    const float* W = by ? W_lin : W_embed;
    float* Out     = by ? lin_out : g_h;

    int tid = threadIdx.x;
    int rowBase = blockIdx.x * 128;

    // A loader: row = tid>>1 (0..127), k-quad = (tid&1)*4
    int arow = tid >> 1;
    int akq  = (tid & 1) * 4;
    // B loader: k-row = tid>>5 (0..7), col = (tid&31)*4
    int brow = tid >> 5;
    int bcol = (tid & 31) * 4;

    int tx = tid & 15;       // 16 col groups of 8
    int ty = tid >> 4;       // 16 row groups of 8

    float acc[8][8];
    #pragma unroll
    for (int i = 0; i < 8; i++)
        #pragma unroll
        for (int j = 0; j < 8; j++) acc[i][j] = 0.f;

    int gr = rowBase + arow;

    // prologue: tile 0
    {
        float4 av = make_float4(0.f, 0.f, 0.f, 0.f);
        if (gr < N) av = *(const float4*)&x[gr * DF + akq];
        As[0][akq + 0][arow] = av.x;
        As[0][akq + 1][arow] = av.y;
        As[0][akq + 2][arow] = av.z;
        As[0][akq + 3][arow] = av.w;
        float4 bv = *(const float4*)&W[brow * DF + bcol];
        *(float4*)&Bs[0][brow][bcol] = bv;
    }
    __syncthreads();

    #pragma unroll
    for (int kt = 0; kt < 16; kt++) {
        int cur = kt & 1;
        float4 nav, nbv;
        if (kt < 15) {
            int k0 = (kt + 1) * 8;
            nav = make_float4(0.f, 0.f, 0.f, 0.f);
            if (gr < N) nav = *(const float4*)&x[gr * DF + k0 + akq];
            nbv = *(const float4*)&W[(k0 + brow) * DF + bcol];
        }
        #pragma unroll
        for (int kk = 0; kk < 8; kk++) {
            float4 a0 = *(const float4*)&As[cur][kk][ty * 8];
            float4 a1 = *(const float4*)&As[cur][kk][ty * 8 + 4];
            float4 b0 = *(const float4*)&Bs[cur][kk][tx * 8];
            float4 b1 = *(const float4*)&Bs[cur][kk][tx * 8 + 4];
            float ar[8] = {a0.x, a0.y, a0.z, a0.w, a1.x, a1.y, a1.z, a1.w};
            float br[8] = {b0.x, b0.y, b0.z, b0.w, b1.x, b1.y, b1.z, b1.w};
            #pragma unroll
            for (int i = 0; i < 8; i++)
                #pragma unroll
                for (int j = 0; j < 8; j++)
                    acc[i][j] += ar[i] * br[j];
        }
        if (kt < 15) {
            int nxt = cur ^ 1;
            As[nxt][akq + 0][arow] = nav.x;
            As[nxt][akq + 1][arow] = nav.y;
            As[nxt][akq + 2][arow] = nav.z;
            As[nxt][akq + 3][arow] = nav.w;
            *(float4*)&Bs[nxt][brow][bcol] = nbv;
            __syncthreads();
        }
    }

    // epilogue
    int cbase = tx * 8;
    float4 bia0 = make_float4(0.f, 0.f, 0.f, 0.f);
    float4 bia1 = make_float4(0.f, 0.f, 0.f, 0.f);
    if (by) {
        bia0 = *(const float4*)&bias[cbase];
        bia1 = *(const float4*)&bias[cbase + 4];
    }
    #pragma unroll
    for (int i = 0; i < 8; i++) {
        int r = rowBase + ty * 8 + i;
        if (r < N) {
            float4 o0 = make_float4(acc[i][0] + bia0.x, acc[i][1] + bia0.y,
                                    acc[i][2] + bia0.z, acc[i][3] + bia0.w);
            float4 o1 = make_float4(acc[i][4] + bia1.x, acc[i][5] + bia1.y,
                                    acc[i][6] + bia1.z, acc[i][7] + bia1.w);
            *(float4*)&Out[r * DF + cbase]     = o0;
            *(float4*)&Out[r * DF + cbase + 4] = o1;
        }
    }
}

// ---------------- per-node attention dots -------------------------
__global__ void dot_kernel(const float* __restrict__ a_src,
                           const float* __restrict__ a_dst,
                           int N)
{
    int warpId = (blockIdx.x * blockDim.x + threadIdx.x) >> 5;
    int lane = threadIdx.x & 31;
    if (warpId >= N) return;

    float4 hv = *(const float4*)&g_h[warpId * DF + lane * 4];
    float4 as = ((const float4*)a_src)[lane];
    float4 ad = ((const float4*)a_dst)[lane];

    float ps = hv.x * as.x + hv.y * as.y + hv.z * as.z + hv.w * as.w;
    float pd = hv.x * ad.x + hv.y * ad.y + hv.z * ad.z + hv.w * ad.w;

    ps += __shfl_xor_sync(0xffffffffu, ps, 1);
    ps += __shfl_xor_sync(0xffffffffu, ps, 2);
    ps += __shfl_xor_sync(0xffffffffu, ps, 4);
    pd += __shfl_xor_sync(0xffffffffu, pd, 1);
    pd += __shfl_xor_sync(0xffffffffu, pd, 2);
    pd += __shfl_xor_sync(0xffffffffu, pd, 4);

    if ((lane & 7) == 0) {
        int head = lane >> 3;
        g_ds[warpId * HEADS + head] = ps;
        g_dd[warpId * HEADS + head] = pd;
    }
}

// ---------------- aggregate: one warp per destination node --------
// acc = sum_e exp(leaky(ds[src]+dd[v])) * h[src];  den = sum_e w
// out[v] = lin(v) + acc/den   (lin already in out)
__global__ void aggregate_kernel(float* __restrict__ out, int N)
{
    int v = (blockIdx.x * blockDim.x + threadIdx.x) >> 5;
    int lane = threadIdx.x & 31;
    if (v >= N) return;
    int head = lane >> 3;

    int b  = g_off[v];
    int e2 = g_off[v + 1];
    float ddv = g_dd[v * HEADS + head];

    float4 acc = make_float4(0.f, 0.f, 0.f, 0.f);
    float den = 0.f;

    int i = b;
    for (; i + 1 < e2; i += 2) {
        int s0 = g_ssrc[i];
        int s1 = g_ssrc[i + 1];
        float z0 = g_ds[s0 * HEADS + head] + ddv;
        float z1 = g_ds[s1 * HEADS + head] + ddv;
        z0 = (z0 >= 0.f) ? z0 : NEG_SLOPE * z0;
        z1 = (z1 >= 0.f) ? z1 : NEG_SLOPE * z1;
        float w0 = __expf(z0);
        float w1 = __expf(z1);
        float4 h0 = *(const float4*)&g_h[s0 * DF + lane * 4];
        float4 h1 = *(const float4*)&g_h[s1 * DF + lane * 4];
        acc.x += w0 * h0.x + w1 * h1.x;
        acc.y += w0 * h0.y + w1 * h1.y;
        acc.z += w0 * h0.z + w1 * h1.z;
        acc.w += w0 * h0.w + w1 * h1.w;
        den += w0 + w1;
    }
    if (i < e2) {
        int s0 = g_ssrc[i];
        float z0 = g_ds[s0 * HEADS + head] + ddv;
        z0 = (z0 >= 0.f) ? z0 : NEG_SLOPE * z0;
        float w0 = __expf(z0);
        float4 h0 = *(const float4*)&g_h[s0 * DF + lane * 4];
        acc.x += w0 * h0.x;
        acc.y += w0 * h0.y;
        acc.z += w0 * h0.z;
        acc.w += w0 * h0.w;
        den += w0;
    }

    float inv = (den > 0.f) ? (1.0f / den) : 0.f;
    float4 o = *(const float4*)&out[v * DF + lane * 4];
    o.x += acc.x * inv;
    o.y += acc.y * inv;
    o.z += acc.z * inv;
    o.w += acc.w * inv;
    *(float4*)&out[v * DF + lane * 4] = o;
}

// ------------------------------------------------------------------
extern "C" void kernel_launch(void* const* d_in, const int* in_sizes, int n_in,
                              void* d_out, int out_size)
{
    const float* x       = (const float*)d_in[0];
    const float* W_embed = (const float*)d_in[1];
    const float* a_src   = (const float*)d_in[2];
    const float* a_dst   = (const float*)d_in[3];
    const float* W_lin   = (const float*)d_in[4];
    const float* bias    = (const float*)d_in[5];
    const int*   src     = (const int*)d_in[6];
    const int*   dst     = (const int*)d_in[7];
    float* out = (float*)d_out;

    int N = in_sizes[0] / DF;
    int E = in_sizes[6];

    // edge CSR sort (independent of GEMM; stream-serialized)
    zero_cnt_kernel<<<(N + 1023) / 1024, 1024>>>(N);
    hist_kernel<<<(E + 255) / 256, 256>>>(dst, E);
    scan_kernel<<<1, 1024>>>(N, E);
    scatter_kernel<<<(E + 255) / 256, 256>>>(src, dst, E);

    // fused dual GEMM: h -> g_h, lin+bias -> d_out
    dim3 ggrid((N + 127) / 128, 2);
    gemm_kernel<<<ggrid, 256>>>(x, W_embed, W_lin, bias, out, N);

    // attention dots
    dot_kernel<<<(N + 7) / 8, 256>>>(a_src, a_dst, N);

    // aggregate + finalize (warp per node, register accumulation)
    aggregate_kernel<<<(N + 7) / 8, 256>>>(out, N);
}

// round 8
// speedup vs baseline: 1.1988x; 1.1988x over previous
#include <cuda_runtime.h>
#include <cuda_bf16.h>
#include <cstdint>

#define MAXN 170000
#define MAXE 1200000
#define DF   128
#define HEADS 4
#define NEG_SLOPE 0.2f

// -------- scratch (device globals; no allocations allowed) --------
__device__ __align__(16) float g_h[MAXN * DF];       // node projections h = x @ W_embed
__device__ __align__(16) float g_ds[MAXN * HEADS];   // dot_src
__device__ __align__(16) float g_dd[MAXN * HEADS];   // dot_dst
__device__ int g_cnt[MAXN];                          // per-dst edge counts
__device__ int g_off[MAXN + 1];                      // CSR offsets
__device__ int g_cur[MAXN];                          // scatter cursors
__device__ int g_ssrc[MAXE];                         // src indices sorted by dst

// ---------------- zero counts -------------------------------------
__global__ void zero_cnt_kernel(int N) {
    int i = blockIdx.x * blockDim.x + threadIdx.x;
    if (i < N) g_cnt[i] = 0;
}

// ---------------- histogram of dst --------------------------------
__global__ void hist_kernel(const int* __restrict__ dst, int E) {
    int e = blockIdx.x * blockDim.x + threadIdx.x;
    if (e < E) atomicAdd(&g_cnt[dst[e]], 1);
}

// ---------------- single-block chunked exclusive scan -------------
__global__ void scan_kernel(int N, int E) {
    __shared__ int sh[1024];
    int t = threadIdx.x;
    int chunk = (N + 1023) >> 10;
    int beg = t * chunk;
    int end = beg + chunk; if (end > N) end = N;

    int s = 0;
    for (int i = beg; i < end; i++) s += g_cnt[i];
    sh[t] = s;
    __syncthreads();
    for (int off = 1; off < 1024; off <<= 1) {
        int v = (t >= off) ? sh[t - off] : 0;
        __syncthreads();
        sh[t] += v;
        __syncthreads();
    }
    int run = sh[t] - s;
    for (int i = beg; i < end; i++) {
        g_off[i] = run;
        g_cur[i] = run;
        run += g_cnt[i];
    }
    if (t == 1023) g_off[N] = E;
}

// ---------------- scatter src into dst-sorted order ---------------
__global__ void scatter_kernel(const int* __restrict__ src,
                               const int* __restrict__ dst, int E) {
    int e = blockIdx.x * blockDim.x + threadIdx.x;
    if (e < E) {
        int d = dst[e];
        int pos = atomicAdd(&g_cur[d], 1);
        g_ssrc[pos] = src[e];
    }
}

// ---------------- bf16-split tensor-core dual GEMM ----------------
// D = A_hi*B_hi + A_hi*B_lo + A_lo*B_hi  (fp32 accum) ~ fp32 accuracy.
// by==0: x @ W_embed -> g_h ; by==1: x @ W_lin (+bias) -> d_out
#define KSTR 40   // padded k-stride in bf16 elems (80B: conflict-free frag LDS)

__device__ __forceinline__ void mma_bf16(float* c, const uint32_t* a,
                                         const uint32_t* b) {
    asm volatile(
        "mma.sync.aligned.m16n8k16.row.col.f32.bf16.bf16.f32 "
        "{%0,%1,%2,%3}, {%4,%5,%6,%7}, {%8,%9}, {%0,%1,%2,%3};\n"
        : "+f"(c[0]), "+f"(c[1]), "+f"(c[2]), "+f"(c[3])
        : "r"(a[0]), "r"(a[1]), "r"(a[2]), "r"(a[3]), "r"(b[0]), "r"(b[1]));
}

__global__ __launch_bounds__(256, 2)
void gemm_kernel(const float* __restrict__ x,
                 const float* __restrict__ W_embed,
                 const float* __restrict__ W_lin,
                 const float* __restrict__ bias,
                 float* __restrict__ lin_out,
                 int N)
{
    __shared__ __nv_bfloat16 As_hi[128 * KSTR];
    __shared__ __nv_bfloat16 As_lo[128 * KSTR];
    __shared__ __nv_bfloat16 Bs_hi[128 * KSTR];   // [n][k] (W transposed)
    __shared__ __nv_bfloat16 Bs_lo[128 * KSTR];

    int by = blockIdx.y;
    const float* W = by ? W_lin : W_embed;
    float* Out     = by ? lin_out : g_h;

    int tid = threadIdx.x;
    int warp = tid >> 5;
    int lane = tid & 31;
    int g = lane >> 2;          // 0..7
    int t = lane & 3;           // 0..3
    int wr = warp >> 1;         // 0..3 : warp row  (32 rows)
    int wc = warp & 1;          // 0..1 : warp col  (64 cols)
    int rowBase = blockIdx.x * 128;

    float acc[2][8][4];
    #pragma unroll
    for (int mt = 0; mt < 2; mt++)
        #pragma unroll
        for (int nt = 0; nt < 8; nt++)
            #pragma unroll
            for (int k = 0; k < 4; k++) acc[mt][nt][k] = 0.f;

    int xrow = tid >> 1;                 // 0..127
    int xkq  = (tid & 1) * 16;           // 0 or 16
    int grow = rowBase + xrow;

    for (int kc = 0; kc < DF; kc += 32) {
        // --- load & split A tile (x[rowBase.., kc..kc+32)) ---
        #pragma unroll
        for (int j = 0; j < 4; j++) {
            float4 v = make_float4(0.f, 0.f, 0.f, 0.f);
            if (grow < N) v = *(const float4*)&x[grow * DF + kc + xkq + j * 4];
            int base = xrow * KSTR + xkq + j * 4;
            __nv_bfloat16 h0 = __float2bfloat16(v.x);
            __nv_bfloat16 h1 = __float2bfloat16(v.y);
            __nv_bfloat16 h2 = __float2bfloat16(v.z);
            __nv_bfloat16 h3 = __float2bfloat16(v.w);
            As_hi[base + 0] = h0; As_hi[base + 1] = h1;
            As_hi[base + 2] = h2; As_hi[base + 3] = h3;
            As_lo[base + 0] = __float2bfloat16(v.x - __bfloat162float(h0));
            As_lo[base + 1] = __float2bfloat16(v.y - __bfloat162float(h1));
            As_lo[base + 2] = __float2bfloat16(v.z - __bfloat162float(h2));
            As_lo[base + 3] = __float2bfloat16(v.w - __bfloat162float(h3));
        }
        // --- load, transpose & split W tile -> Bs[n][k] ---
        #pragma unroll
        for (int i = 0; i < 16; i++) {
            int idx = tid + i * 256;            // 0..4095
            int kk = idx >> 7;                  // 0..31
            int nn = idx & 127;
            float w = W[(kc + kk) * DF + nn];
            __nv_bfloat16 hw = __float2bfloat16(w);
            Bs_hi[nn * KSTR + kk] = hw;
            Bs_lo[nn * KSTR + kk] = __float2bfloat16(w - __bfloat162float(hw));
        }
        __syncthreads();

        #pragma unroll
        for (int ks = 0; ks < 32; ks += 16) {
            uint32_t ah[2][4], al[2][4];
            #pragma unroll
            for (int mt = 0; mt < 2; mt++) {
                int m0 = wr * 32 + mt * 16;
                int r0 = (m0 + g) * KSTR + ks + 2 * t;
                int r1 = (m0 + g + 8) * KSTR + ks + 2 * t;
                ah[mt][0] = *(const uint32_t*)&As_hi[r0];
                ah[mt][1] = *(const uint32_t*)&As_hi[r1];
                ah[mt][2] = *(const uint32_t*)&As_hi[r0 + 8];
                ah[mt][3] = *(const uint32_t*)&As_hi[r1 + 8];
                al[mt][0] = *(const uint32_t*)&As_lo[r0];
                al[mt][1] = *(const uint32_t*)&As_lo[r1];
                al[mt][2] = *(const uint32_t*)&As_lo[r0 + 8];
                al[mt][3] = *(const uint32_t*)&As_lo[r1 + 8];
            }
            #pragma unroll
            for (int nt = 0; nt < 8; nt++) {
                int n0 = wc * 64 + nt * 8;
                int bidx = (n0 + g) * KSTR + ks + 2 * t;
                uint32_t bh[2], bl[2];
                bh[0] = *(const uint32_t*)&Bs_hi[bidx];
                bh[1] = *(const uint32_t*)&Bs_hi[bidx + 8];
                bl[0] = *(const uint32_t*)&Bs_lo[bidx];
                bl[1] = *(const uint32_t*)&Bs_lo[bidx + 8];
                #pragma unroll
                for (int mt = 0; mt < 2; mt++) {
                    mma_bf16(acc[mt][nt], ah[mt], bh);   // hi*hi
                    mma_bf16(acc[mt][nt], ah[mt], bl);   // hi*lo
                    mma_bf16(acc[mt][nt], al[mt], bh);   // lo*hi
                }
            }
        }
        __syncthreads();
    }

    // --- epilogue ---
    #pragma unroll
    for (int nt = 0; nt < 8; nt++) {
        int col = wc * 64 + nt * 8 + 2 * t;
        float b0 = 0.f, b1 = 0.f;
        if (by) { b0 = bias[col]; b1 = bias[col + 1]; }
        #pragma unroll
        for (int mt = 0; mt < 2; mt++) {
            int r0 = rowBase + wr * 32 + mt * 16 + g;
            if (r0 < N) {
                float2 o = make_float2(acc[mt][nt][0] + b0, acc[mt][nt][1] + b1);
                *(float2*)&Out[r0 * DF + col] = o;
            }
            int r1 = r0 + 8;
            if (r1 < N) {
                float2 o = make_float2(acc[mt][nt][2] + b0, acc[mt][nt][3] + b1);
                *(float2*)&Out[r1 * DF + col] = o;
            }
        }
    }
}

// ---------------- per-node attention dots -------------------------
__global__ void dot_kernel(const float* __restrict__ a_src,
                           const float* __restrict__ a_dst,
                           int N)
{
    int warpId = (blockIdx.x * blockDim.x + threadIdx.x) >> 5;
    int lane = threadIdx.x & 31;
    if (warpId >= N) return;

    float4 hv = *(const float4*)&g_h[warpId * DF + lane * 4];
    float4 as = ((const float4*)a_src)[lane];
    float4 ad = ((const float4*)a_dst)[lane];

    float ps = hv.x * as.x + hv.y * as.y + hv.z * as.z + hv.w * as.w;
    float pd = hv.x * ad.x + hv.y * ad.y + hv.z * ad.z + hv.w * ad.w;

    ps += __shfl_xor_sync(0xffffffffu, ps, 1);
    ps += __shfl_xor_sync(0xffffffffu, ps, 2);
    ps += __shfl_xor_sync(0xffffffffu, ps, 4);
    pd += __shfl_xor_sync(0xffffffffu, pd, 1);
    pd += __shfl_xor_sync(0xffffffffu, pd, 2);
    pd += __shfl_xor_sync(0xffffffffu, pd, 4);

    if ((lane & 7) == 0) {
        int head = lane >> 3;
        g_ds[warpId * HEADS + head] = ps;
        g_dd[warpId * HEADS + head] = pd;
    }
}

// ---------------- aggregate: one warp per destination node --------
// unroll-4 with prefetched indices -> 4 independent 512B gathers in flight
__global__ void aggregate_kernel(float* __restrict__ out, int N)
{
    int v = (blockIdx.x * blockDim.x + threadIdx.x) >> 5;
    int lane = threadIdx.x & 31;
    if (v >= N) return;
    int head = lane >> 3;
    int c4 = lane * 4;

    int b  = g_off[v];
    int e2 = g_off[v + 1];
    float ddv = g_dd[v * HEADS + head];

    float4 acc = make_float4(0.f, 0.f, 0.f, 0.f);
    float den = 0.f;

    int i = b;
    for (; i + 4 <= e2; i += 4) {
        int s0 = __ldg(&g_ssrc[i]);
        int s1 = __ldg(&g_ssrc[i + 1]);
        int s2 = __ldg(&g_ssrc[i + 2]);
        int s3 = __ldg(&g_ssrc[i + 3]);
        float z0 = __ldg(&g_ds[s0 * HEADS + head]) + ddv;
        float z1 = __ldg(&g_ds[s1 * HEADS + head]) + ddv;
        float z2 = __ldg(&g_ds[s2 * HEADS + head]) + ddv;
        float z3 = __ldg(&g_ds[s3 * HEADS + head]) + ddv;
        float4 h0 = __ldg((const float4*)&g_h[s0 * DF + c4]);
        float4 h1 = __ldg((const float4*)&g_h[s1 * DF + c4]);
        float4 h2 = __ldg((const float4*)&g_h[s2 * DF + c4]);
        float4 h3 = __ldg((const float4*)&g_h[s3 * DF + c4]);
        z0 = (z0 >= 0.f) ? z0 : NEG_SLOPE * z0;
        z1 = (z1 >= 0.f) ? z1 : NEG_SLOPE * z1;
        z2 = (z2 >= 0.f) ? z2 : NEG_SLOPE * z2;
        z3 = (z3 >= 0.f) ? z3 : NEG_SLOPE * z3;
        float w0 = __expf(z0), w1 = __expf(z1);
        float w2 = __expf(z2), w3 = __expf(z3);
        acc.x += w0 * h0.x + w1 * h1.x + w2 * h2.x + w3 * h3.x;
        acc.y += w0 * h0.y + w1 * h1.y + w2 * h2.y + w3 * h3.y;
        acc.z += w0 * h0.z + w1 * h1.z + w2 * h2.z + w3 * h3.z;
        acc.w += w0 * h0.w + w1 * h1.w + w2 * h2.w + w3 * h3.w;
        den += (w0 + w1) + (w2 + w3);
    }
    for (; i < e2; i++) {
        int s0 = __ldg(&g_ssrc[i]);
        float z0 = __ldg(&g_ds[s0 * HEADS + head]) + ddv;
        z0 = (z0 >= 0.f) ? z0 : NEG_SLOPE * z0;
        float w0 = __expf(z0);
        float4 h0 = __ldg((const float4*)&g_h[s0 * DF + c4]);
        acc.x += w0 * h0.x;
        acc.y += w0 * h0.y;
        acc.z += w0 * h0.z;
        acc.w += w0 * h0.w;
        den += w0;
    }

    float inv = (den > 0.f) ? (1.0f / den) : 0.f;
    float4 o = *(const float4*)&out[v * DF + c4];
    o.x += acc.x * inv;
    o.y += acc.y * inv;
    o.z += acc.z * inv;
    o.w += acc.w * inv;
    *(float4*)&out[v * DF + c4] = o;
}

// ------------------------------------------------------------------
extern "C" void kernel_launch(void* const* d_in, const int* in_sizes, int n_in,
                              void* d_out, int out_size)
{
    const float* x       = (const float*)d_in[0];
    const float* W_embed = (const float*)d_in[1];
    const float* a_src   = (const float*)d_in[2];
    const float* a_dst   = (const float*)d_in[3];
    const float* W_lin   = (const float*)d_in[4];
    const float* bias    = (const float*)d_in[5];
    const int*   src     = (const int*)d_in[6];
    const int*   dst     = (const int*)d_in[7];
    float* out = (float*)d_out;

    int N = in_sizes[0] / DF;
    int E = in_sizes[6];

    // edge CSR sort
    zero_cnt_kernel<<<(N + 1023) / 1024, 1024>>>(N);
    hist_kernel<<<(E + 255) / 256, 256>>>(dst, E);
    scan_kernel<<<1, 1024>>>(N, E);
    scatter_kernel<<<(E + 255) / 256, 256>>>(src, dst, E);

    // bf16-split tensor dual GEMM: h -> g_h, lin+bias -> d_out
    dim3 ggrid((N + 127) / 128, 2);
    gemm_kernel<<<ggrid, 256>>>(x, W_embed, W_lin, bias, out, N);

    // attention dots
    dot_kernel<<<(N + 7) / 8, 256>>>(a_src, a_dst, N);

    // aggregate + finalize
    aggregate_kernel<<<(N + 7) / 8, 256>>>(out, N);
}

// round 9
// speedup vs baseline: 1.5422x; 1.2865x over previous
#include <cuda_runtime.h>
#include <cuda_bf16.h>
#include <cstdint>

#define MAXN 170000
#define DF   128
#define HEADS 4
#define NEG_SLOPE 0.2f

// -------- scratch (device globals; no allocations allowed) --------
__device__ __align__(16) float g_h[MAXN * DF];       // node projections h = x @ W_embed
__device__ __align__(16) float g_acc[MAXN * DF];     // unnormalized aggregation
__device__ __align__(16) float g_ds[MAXN * HEADS];   // dot_src
__device__ __align__(16) float g_dd[MAXN * HEADS];   // dot_dst
__device__ __align__(16) float g_den[MAXN * HEADS];  // softmax denominators

// ---------------- zero accumulators -------------------------------
__global__ void zero_kernel(int n) {
    int idx = blockIdx.x * blockDim.x + threadIdx.x;
    int acc4 = n * 32;
    float4 z = make_float4(0.f, 0.f, 0.f, 0.f);
    if (idx < acc4) {
        ((float4*)g_acc)[idx] = z;
    } else if (idx < acc4 + n) {
        ((float4*)g_den)[idx - acc4] = z;
    }
}

// ---------------- bf16-split tensor-core dual GEMM ----------------
// D = A_hi*B_hi + A_hi*B_lo + A_lo*B_hi  (fp32 accum) ~ fp32 accuracy.
// by==0: x @ W_embed -> g_h ; by==1: x @ W_lin (+bias) -> d_out
#define KSTR 40   // padded k-stride in bf16 elems (80B: conflict-free frag LDS)

__device__ __forceinline__ void mma_bf16(float* c, const uint32_t* a,
                                         const uint32_t* b) {
    asm volatile(
        "mma.sync.aligned.m16n8k16.row.col.f32.bf16.bf16.f32 "
        "{%0,%1,%2,%3}, {%4,%5,%6,%7}, {%8,%9}, {%0,%1,%2,%3};\n"
        : "+f"(c[0]), "+f"(c[1]), "+f"(c[2]), "+f"(c[3])
        : "r"(a[0]), "r"(a[1]), "r"(a[2]), "r"(a[3]), "r"(b[0]), "r"(b[1]));
}

__global__ __launch_bounds__(256, 2)
void gemm_kernel(const float* __restrict__ x,
                 const float* __restrict__ W_embed,
                 const float* __restrict__ W_lin,
                 const float* __restrict__ bias,
                 float* __restrict__ lin_out,
                 int N)
{
    __shared__ __nv_bfloat16 As_hi[128 * KSTR];
    __shared__ __nv_bfloat16 As_lo[128 * KSTR];
    __shared__ __nv_bfloat16 Bs_hi[128 * KSTR];   // [n][k] (W transposed)
    __shared__ __nv_bfloat16 Bs_lo[128 * KSTR];

    int by = blockIdx.y;
    const float* W = by ? W_lin : W_embed;
    float* Out     = by ? lin_out : g_h;

    int tid = threadIdx.x;
    int warp = tid >> 5;
    int lane = tid & 31;
    int g = lane >> 2;          // 0..7
    int t = lane & 3;           // 0..3
    int wr = warp >> 1;         // 0..3 : warp row  (32 rows)
    int wc = warp & 1;          // 0..1 : warp col  (64 cols)
    int rowBase = blockIdx.x * 128;

    float acc[2][8][4];
    #pragma unroll
    for (int mt = 0; mt < 2; mt++)
        #pragma unroll
        for (int nt = 0; nt < 8; nt++)
            #pragma unroll
            for (int k = 0; k < 4; k++) acc[mt][nt][k] = 0.f;

    int xrow = tid >> 1;                 // 0..127
    int xkq  = (tid & 1) * 16;           // 0 or 16
    int grow = rowBase + xrow;

    for (int kc = 0; kc < DF; kc += 32) {
        // --- load & split A tile ---
        #pragma unroll
        for (int j = 0; j < 4; j++) {
            float4 v = make_float4(0.f, 0.f, 0.f, 0.f);
            if (grow < N) v = *(const float4*)&x[grow * DF + kc + xkq + j * 4];
            int base = xrow * KSTR + xkq + j * 4;
            __nv_bfloat16 h0 = __float2bfloat16(v.x);
            __nv_bfloat16 h1 = __float2bfloat16(v.y);
            __nv_bfloat16 h2 = __float2bfloat16(v.z);
            __nv_bfloat16 h3 = __float2bfloat16(v.w);
            As_hi[base + 0] = h0; As_hi[base + 1] = h1;
            As_hi[base + 2] = h2; As_hi[base + 3] = h3;
            As_lo[base + 0] = __float2bfloat16(v.x - __bfloat162float(h0));
            As_lo[base + 1] = __float2bfloat16(v.y - __bfloat162float(h1));
            As_lo[base + 2] = __float2bfloat16(v.z - __bfloat162float(h2));
            As_lo[base + 3] = __float2bfloat16(v.w - __bfloat162float(h3));
        }
        // --- load, transpose & split W tile -> Bs[n][k] ---
        #pragma unroll
        for (int i = 0; i < 16; i++) {
            int idx = tid + i * 256;            // 0..4095
            int kk = idx >> 7;                  // 0..31
            int nn = idx & 127;
            float w = W[(kc + kk) * DF + nn];
            __nv_bfloat16 hw = __float2bfloat16(w);
            Bs_hi[nn * KSTR + kk] = hw;
            Bs_lo[nn * KSTR + kk] = __float2bfloat16(w - __bfloat162float(hw));
        }
        __syncthreads();

        #pragma unroll
        for (int ks = 0; ks < 32; ks += 16) {
            uint32_t ah[2][4], al[2][4];
            #pragma unroll
            for (int mt = 0; mt < 2; mt++) {
                int m0 = wr * 32 + mt * 16;
                int r0 = (m0 + g) * KSTR + ks + 2 * t;
                int r1 = (m0 + g + 8) * KSTR + ks + 2 * t;
                ah[mt][0] = *(const uint32_t*)&As_hi[r0];
                ah[mt][1] = *(const uint32_t*)&As_hi[r1];
                ah[mt][2] = *(const uint32_t*)&As_hi[r0 + 8];
                ah[mt][3] = *(const uint32_t*)&As_hi[r1 + 8];
                al[mt][0] = *(const uint32_t*)&As_lo[r0];
                al[mt][1] = *(const uint32_t*)&As_lo[r1];
                al[mt][2] = *(const uint32_t*)&As_lo[r0 + 8];
                al[mt][3] = *(const uint32_t*)&As_lo[r1 + 8];
            }
            #pragma unroll
            for (int nt = 0; nt < 8; nt++) {
                int n0 = wc * 64 + nt * 8;
                int bidx = (n0 + g) * KSTR + ks + 2 * t;
                uint32_t bh[2], bl[2];
                bh[0] = *(const uint32_t*)&Bs_hi[bidx];
                bh[1] = *(const uint32_t*)&Bs_hi[bidx + 8];
                bl[0] = *(const uint32_t*)&Bs_lo[bidx];
                bl[1] = *(const uint32_t*)&Bs_lo[bidx + 8];
                #pragma unroll
                for (int mt = 0; mt < 2; mt++) {
                    mma_bf16(acc[mt][nt], ah[mt], bh);   // hi*hi
                    mma_bf16(acc[mt][nt], ah[mt], bl);   // hi*lo
                    mma_bf16(acc[mt][nt], al[mt], bh);   // lo*hi
                }
            }
        }
        __syncthreads();
    }

    // --- epilogue ---
    #pragma unroll
    for (int nt = 0; nt < 8; nt++) {
        int col = wc * 64 + nt * 8 + 2 * t;
        float b0 = 0.f, b1 = 0.f;
        if (by) { b0 = bias[col]; b1 = bias[col + 1]; }
        #pragma unroll
        for (int mt = 0; mt < 2; mt++) {
            int r0 = rowBase + wr * 32 + mt * 16 + g;
            if (r0 < N) {
                float2 o = make_float2(acc[mt][nt][0] + b0, acc[mt][nt][1] + b1);
                *(float2*)&Out[r0 * DF + col] = o;
            }
            int r1 = r0 + 8;
            if (r1 < N) {
                float2 o = make_float2(acc[mt][nt][2] + b0, acc[mt][nt][3] + b1);
                *(float2*)&Out[r1 * DF + col] = o;
            }
        }
    }
}

// ---------------- per-node attention dots -------------------------
__global__ void dot_kernel(const float* __restrict__ a_src,
                           const float* __restrict__ a_dst,
                           int N)
{
    int warpId = (blockIdx.x * blockDim.x + threadIdx.x) >> 5;
    int lane = threadIdx.x & 31;
    if (warpId >= N) return;

    float4 hv = *(const float4*)&g_h[warpId * DF + lane * 4];
    float4 as = ((const float4*)a_src)[lane];
    float4 ad = ((const float4*)a_dst)[lane];

    float ps = hv.x * as.x + hv.y * as.y + hv.z * as.z + hv.w * as.w;
    float pd = hv.x * ad.x + hv.y * ad.y + hv.z * ad.z + hv.w * ad.w;

    ps += __shfl_xor_sync(0xffffffffu, ps, 1);
    ps += __shfl_xor_sync(0xffffffffu, ps, 2);
    ps += __shfl_xor_sync(0xffffffffu, ps, 4);
    pd += __shfl_xor_sync(0xffffffffu, pd, 1);
    pd += __shfl_xor_sync(0xffffffffu, pd, 2);
    pd += __shfl_xor_sync(0xffffffffu, pd, 4);

    if ((lane & 7) == 0) {
        int head = lane >> 3;
        g_ds[warpId * HEADS + head] = ps;
        g_dd[warpId * HEADS + head] = pd;
    }
}

// ---------------- edge pass (warp per edge, atomic scatter) -------
// acc[dst] += e * h[src]; den[dst] += e.  (softmax shift-invariant)
__global__ void edge_kernel(const int* __restrict__ src,
                            const int* __restrict__ dst,
                            int E)
{
    int warpId = (blockIdx.x * blockDim.x + threadIdx.x) >> 5;
    int lane = threadIdx.x & 31;
    if (warpId >= E) return;

    int s = src[warpId];
    int d = dst[warpId];
    int head = lane >> 3;

    float z = g_ds[s * HEADS + head] + g_dd[d * HEADS + head];
    z = (z >= 0.f) ? z : NEG_SLOPE * z;
    float w = __expf(z);

    if ((lane & 7) == 0)
        atomicAdd(&g_den[d * HEADS + head], w);

    float4 v = *(const float4*)&g_h[s * DF + lane * 4];
    float a0 = w * v.x, a1 = w * v.y, a2 = w * v.z, a3 = w * v.w;
    float* p = &g_acc[d * DF + lane * 4];
    asm volatile("red.global.add.v4.f32 [%0], {%1, %2, %3, %4};"
                 :: "l"(p), "f"(a0), "f"(a1), "f"(a2), "f"(a3) : "memory");
}

// ---------------- finalize ----------------------------------------
__global__ void final_kernel(float* __restrict__ out, int N)
{
    int idx = blockIdx.x * blockDim.x + threadIdx.x;   // float4 index over N*32
    if (idx >= N * 32) return;
    int n = idx >> 5;
    int head = (idx >> 3) & 3;
    float den = g_den[n * HEADS + head];
    float inv = (den > 0.f) ? (1.0f / den) : 0.f;
    float4 a = ((const float4*)g_acc)[idx];
    float4 o = ((float4*)out)[idx];
    o.x += a.x * inv;
    o.y += a.y * inv;
    o.z += a.z * inv;
    o.w += a.w * inv;
    ((float4*)out)[idx] = o;
}

// ------------------------------------------------------------------
extern "C" void kernel_launch(void* const* d_in, const int* in_sizes, int n_in,
                              void* d_out, int out_size)
{
    const float* x       = (const float*)d_in[0];
    const float* W_embed = (const float*)d_in[1];
    const float* a_src   = (const float*)d_in[2];
    const float* a_dst   = (const float*)d_in[3];
    const float* W_lin   = (const float*)d_in[4];
    const float* bias    = (const float*)d_in[5];
    const int*   src     = (const int*)d_in[6];
    const int*   dst     = (const int*)d_in[7];
    float* out = (float*)d_out;

    int N = in_sizes[0] / DF;
    int E = in_sizes[6];

    // 1. zero accumulators
    int z4 = N * 33;
    zero_kernel<<<(z4 + 255) / 256, 256>>>(N);

    // 2. bf16-split tensor dual GEMM: h -> g_h, lin+bias -> d_out
    dim3 ggrid((N + 127) / 128, 2);
    gemm_kernel<<<ggrid, 256>>>(x, W_embed, W_lin, bias, out, N);

    // 3. attention dots (one warp per node)
    dot_kernel<<<(N + 7) / 8, 256>>>(a_src, a_dst, N);

    // 4. edge pass (one warp per edge)
    edge_kernel<<<(E + 7) / 8, 256>>>(src, dst, E);

    // 5. finalize
    final_kernel<<<(N * 32 + 255) / 256, 256>>>(out, N);
}

// round 12
// speedup vs baseline: 1.6373x; 1.0617x over previous
#include <cuda_runtime.h>
#include <cuda_bf16.h>
#include <cstdint>

#define MAXN 170000
#define DF   128
#define HEADS 4
#define NEG_SLOPE 0.2f

// -------- scratch (device globals; no allocations allowed) --------
// HEAD-MAJOR layouts: g_h/g_acc = [head][node][32], g_ds/dd/den = [head][node]
__device__ __align__(16) float g_h[MAXN * DF];
__device__ __align__(16) float g_acc[MAXN * DF];
__device__ __align__(16) float g_ds[MAXN * HEADS];
__device__ __align__(16) float g_dd[MAXN * HEADS];
__device__ __align__(16) float g_den[MAXN * HEADS];

// ---------------- zero accumulators -------------------------------
__global__ void zero_kernel(int n) {
    int idx = blockIdx.x * blockDim.x + threadIdx.x;
    int acc4 = n * 32;
    float4 z = make_float4(0.f, 0.f, 0.f, 0.f);
    if (idx < acc4) {
        ((float4*)g_acc)[idx] = z;
    } else if (idx < acc4 + n) {
        ((float4*)g_den)[idx - acc4] = z;
    }
}

// ---------------- bf16-split tensor-core dual GEMM ----------------
// D = A_hi*B_hi + A_hi*B_lo + A_lo*B_hi  (fp32 accum) ~ fp32 accuracy.
// by==0: x @ W_embed -> g_h (HEAD-MAJOR) ; by==1: x @ W_lin (+bias) -> d_out
#define KSTR 40   // padded k-stride in bf16 elems

__device__ __forceinline__ void mma_bf16(float* c, const uint32_t* a,
                                         const uint32_t* b) {
    asm volatile(
        "mma.sync.aligned.m16n8k16.row.col.f32.bf16.bf16.f32 "
        "{%0,%1,%2,%3}, {%4,%5,%6,%7}, {%8,%9}, {%0,%1,%2,%3};\n"
        : "+f"(c[0]), "+f"(c[1]), "+f"(c[2]), "+f"(c[3])
        : "r"(a[0]), "r"(a[1]), "r"(a[2]), "r"(a[3]), "r"(b[0]), "r"(b[1]));
}

__device__ __forceinline__ uint32_t pack2(__nv_bfloat16 a, __nv_bfloat16 b) {
    __nv_bfloat162 t;
    t.x = a; t.y = b;
    return *(uint32_t*)&t;
}

__global__ __launch_bounds__(256, 2)
void gemm_kernel(const float* __restrict__ x,
                 const float* __restrict__ W_embed,
                 const float* __restrict__ W_lin,
                 const float* __restrict__ bias,
                 float* __restrict__ lin_out,
                 int N)
{
    __shared__ __nv_bfloat16 As_hi[128 * KSTR];
    __shared__ __nv_bfloat16 As_lo[128 * KSTR];
    __shared__ __nv_bfloat16 Bs_hi[128 * KSTR];   // [n][k] (W transposed)
    __shared__ __nv_bfloat16 Bs_lo[128 * KSTR];

    int by = blockIdx.y;
    const float* W = by ? W_lin : W_embed;

    int tid = threadIdx.x;
    int warp = tid >> 5;
    int lane = tid & 31;
    int g = lane >> 2;          // 0..7
    int t = lane & 3;           // 0..3
    int wr = warp >> 1;         // 0..3
    int wc = warp & 1;          // 0..1
    int rowBase = blockIdx.x * 128;

    float acc[2][8][4];
    #pragma unroll
    for (int mt = 0; mt < 2; mt++)
        #pragma unroll
        for (int nt = 0; nt < 8; nt++)
            #pragma unroll
            for (int k = 0; k < 4; k++) acc[mt][nt][k] = 0.f;

    int xrow = tid >> 1;                 // 0..127
    int xkq  = (tid & 1) * 16;           // 0 or 16
    int grow = rowBase + xrow;

    for (int kc = 0; kc < DF; kc += 32) {
        // --- load & split A tile (STS.32 pairs) ---
        #pragma unroll
        for (int j = 0; j < 4; j++) {
            float4 v = make_float4(0.f, 0.f, 0.f, 0.f);
            if (grow < N) v = *(const float4*)&x[grow * DF + kc + xkq + j * 4];
            int base = xrow * KSTR + xkq + j * 4;   // even
            __nv_bfloat16 h0 = __float2bfloat16(v.x);
            __nv_bfloat16 h1 = __float2bfloat16(v.y);
            __nv_bfloat16 h2 = __float2bfloat16(v.z);
            __nv_bfloat16 h3 = __float2bfloat16(v.w);
            *(uint32_t*)&As_hi[base]     = pack2(h0, h1);
            *(uint32_t*)&As_hi[base + 2] = pack2(h2, h3);
            *(uint32_t*)&As_lo[base] = pack2(
                __float2bfloat16(v.x - __bfloat162float(h0)),
                __float2bfloat16(v.y - __bfloat162float(h1)));
            *(uint32_t*)&As_lo[base + 2] = pack2(
                __float2bfloat16(v.z - __bfloat162float(h2)),
                __float2bfloat16(v.w - __bfloat162float(h3)));
        }
        // --- load, transpose & split W tile -> Bs[n][k] (STS.32 pairs) ---
        #pragma unroll
        for (int i = 0; i < 8; i++) {
            int idx = tid + i * 256;            // 0..2047
            int kk2 = idx >> 7;                 // 0..15
            int nn  = idx & 127;
            int k0 = 2 * kk2;
            float w0 = W[(kc + k0) * DF + nn];
            float w1 = W[(kc + k0 + 1) * DF + nn];
            __nv_bfloat16 hw0 = __float2bfloat16(w0);
            __nv_bfloat16 hw1 = __float2bfloat16(w1);
            int base = nn * KSTR + k0;          // even
            *(uint32_t*)&Bs_hi[base] = pack2(hw0, hw1);
            *(uint32_t*)&Bs_lo[base] = pack2(
                __float2bfloat16(w0 - __bfloat162float(hw0)),
                __float2bfloat16(w1 - __bfloat162float(hw1)));
        }
        __syncthreads();

        #pragma unroll
        for (int ks = 0; ks < 32; ks += 16) {
            uint32_t ah[2][4], al[2][4];
            #pragma unroll
            for (int mt = 0; mt < 2; mt++) {
                int m0 = wr * 32 + mt * 16;
                int r0 = (m0 + g) * KSTR + ks + 2 * t;
                int r1 = (m0 + g + 8) * KSTR + ks + 2 * t;
                ah[mt][0] = *(const uint32_t*)&As_hi[r0];
                ah[mt][1] = *(const uint32_t*)&As_hi[r1];
                ah[mt][2] = *(const uint32_t*)&As_hi[r0 + 8];
                ah[mt][3] = *(const uint32_t*)&As_hi[r1 + 8];
                al[mt][0] = *(const uint32_t*)&As_lo[r0];
                al[mt][1] = *(const uint32_t*)&As_lo[r1];
                al[mt][2] = *(const uint32_t*)&As_lo[r0 + 8];
                al[mt][3] = *(const uint32_t*)&As_lo[r1 + 8];
            }
            #pragma unroll
            for (int nt = 0; nt < 8; nt++) {
                int n0 = wc * 64 + nt * 8;
                int bidx = (n0 + g) * KSTR + ks + 2 * t;
                uint32_t bh[2], bl[2];
                bh[0] = *(const uint32_t*)&Bs_hi[bidx];
                bh[1] = *(const uint32_t*)&Bs_hi[bidx + 8];
                bl[0] = *(const uint32_t*)&Bs_lo[bidx];
                bl[1] = *(const uint32_t*)&Bs_lo[bidx + 8];
                #pragma unroll
                for (int mt = 0; mt < 2; mt++) {
                    mma_bf16(acc[mt][nt], ah[mt], bh);   // hi*hi
                    mma_bf16(acc[mt][nt], ah[mt], bl);   // hi*lo
                    mma_bf16(acc[mt][nt], al[mt], bh);   // lo*hi
                }
            }
        }
        __syncthreads();
    }

    // --- epilogue ---
    int N32 = N * 32;
    #pragma unroll
    for (int nt = 0; nt < 8; nt++) {
        int col = wc * 64 + nt * 8 + 2 * t;
        float b0 = 0.f, b1 = 0.f;
        if (by) { b0 = bias[col]; b1 = bias[col + 1]; }
        int hd = col >> 5;
        int ch = col & 31;
        #pragma unroll
        for (int mt = 0; mt < 2; mt++) {
            int r0 = rowBase + wr * 32 + mt * 16 + g;
            if (r0 < N) {
                float2 o = make_float2(acc[mt][nt][0] + b0, acc[mt][nt][1] + b1);
                if (by) *(float2*)&lin_out[r0 * DF + col] = o;
                else    *(float2*)&g_h[hd * N32 + r0 * 32 + ch] = o;
            }
            int r1 = r0 + 8;
            if (r1 < N) {
                float2 o = make_float2(acc[mt][nt][2] + b0, acc[mt][nt][3] + b1);
                if (by) *(float2*)&lin_out[r1 * DF + col] = o;
                else    *(float2*)&g_h[hd * N32 + r1 * 32 + ch] = o;
            }
        }
    }
}

// ---------------- per-node attention dots (head-major h) ----------
__global__ void dot_kernel(const float* __restrict__ a_src,
                           const float* __restrict__ a_dst,
                           int N)
{
    int n = (blockIdx.x * blockDim.x + threadIdx.x) >> 5;
    int lane = threadIdx.x & 31;
    if (n >= N) return;
    int hd = lane >> 3;
    int lg = lane & 7;

    float4 hv = *(const float4*)&g_h[hd * (N * 32) + n * 32 + lg * 4];
    float4 as = ((const float4*)a_src)[lane];   // element hd*32+lg*4 == lane*4
    float4 ad = ((const float4*)a_dst)[lane];

    float ps = hv.x * as.x + hv.y * as.y + hv.z * as.z + hv.w * as.w;
    float pd = hv.x * ad.x + hv.y * ad.y + hv.z * ad.z + hv.w * ad.w;

    ps += __shfl_xor_sync(0xffffffffu, ps, 1);
    ps += __shfl_xor_sync(0xffffffffu, ps, 2);
    ps += __shfl_xor_sync(0xffffffffu, ps, 4);
    pd += __shfl_xor_sync(0xffffffffu, pd, 1);
    pd += __shfl_xor_sync(0xffffffffu, pd, 2);
    pd += __shfl_xor_sync(0xffffffffu, pd, 4);

    if (lg == 0) {
        g_ds[hd * N + n] = ps;
        g_dd[hd * N + n] = pd;
    }
}

// ---------------- per-head edge pass ------------------------------
// 4 edges per warp, 8 lanes per edge (one 128B line per gather/red).
// Per-head working set (~55 MB) is L2-resident.
__global__ void edge_head_kernel(const int* __restrict__ src,
                                 const int* __restrict__ dst,
                                 int E, int N, int hd)
{
    int warpId = (blockIdx.x * blockDim.x + threadIdx.x) >> 5;
    int lane = threadIdx.x & 31;
    int base = warpId * 4;
    if (base >= E) return;
    int sub = lane >> 3;
    int lg  = lane & 7;

    // lanes 0..3 compute per-edge scalars for edges base+0..base+3
    int e4 = base + (lane & 3);
    int s4 = 0, d4 = 0;
    float wexp = 0.f;
    if (e4 < E) {
        s4 = src[e4];
        d4 = dst[e4];
        float z = g_ds[hd * N + s4] + g_dd[hd * N + d4];
        z = (z >= 0.f) ? z : NEG_SLOPE * z;
        wexp = __expf(z);
    }
    int   s = __shfl_sync(0xffffffffu, s4, sub);
    int   d = __shfl_sync(0xffffffffu, d4, sub);
    float w = __shfl_sync(0xffffffffu, wexp, sub);

    int e = base + sub;
    if (e >= E) return;

    if (lg == 0)
        atomicAdd(&g_den[hd * N + d], w);

    int N32 = N * 32;
    float4 v = *(const float4*)&g_h[hd * N32 + s * 32 + lg * 4];
    float a0 = w * v.x, a1 = w * v.y, a2 = w * v.z, a3 = w * v.w;
    float* p = &g_acc[hd * N32 + d * 32 + lg * 4];
    asm volatile("red.global.add.v4.f32 [%0], {%1, %2, %3, %4};"
                 :: "l"(p), "f"(a0), "f"(a1), "f"(a2), "f"(a3) : "memory");
}

// ---------------- finalize (head-major acc -> row-major out) ------
__global__ void final_kernel(float* __restrict__ out, int N)
{
    int idx = blockIdx.x * blockDim.x + threadIdx.x;   // float4 index over N*32
    if (idx >= N * 32) return;
    int n = idx >> 5;
    int q = idx & 31;
    int hd = q >> 3;
    int j  = q & 7;
    float den = g_den[hd * N + n];
    float inv = (den > 0.f) ? (1.0f / den) : 0.f;
    float4 a = ((const float4*)g_acc)[hd * (N * 8) + n * 8 + j];
    float4 o = ((float4*)out)[idx];
    o.x += a.x * inv;
    o.y += a.y * inv;
    o.z += a.z * inv;
    o.w += a.w * inv;
    ((float4*)out)[idx] = o;
}

// ------------------------------------------------------------------
extern "C" void kernel_launch(void* const* d_in, const int* in_sizes, int n_in,
                              void* d_out, int out_size)
{
    const float* x       = (const float*)d_in[0];
    const float* W_embed = (const float*)d_in[1];
    const float* a_src   = (const float*)d_in[2];
    const float* a_dst   = (const float*)d_in[3];
    const float* W_lin   = (const float*)d_in[4];
    const float* bias    = (const float*)d_in[5];
    const int*   src     = (const int*)d_in[6];
    const int*   dst     = (const int*)d_in[7];
    float* out = (float*)d_out;

    int N = in_sizes[0] / DF;
    int E = in_sizes[6];

    // 1. zero accumulators
    int z4 = N * 33;
    zero_kernel<<<(z4 + 255) / 256, 256>>>(N);

    // 2. bf16-split tensor dual GEMM: h -> g_h (head-major), lin+bias -> d_out
    dim3 ggrid((N + 127) / 128, 2);
    gemm_kernel<<<ggrid, 256>>>(x, W_embed, W_lin, bias, out, N);

    // 3. attention dots
    dot_kernel<<<(N + 7) / 8, 256>>>(a_src, a_dst, N);

    // 4. edge passes, one head at a time (L2-resident working set)
    int eblocks = (E + 31) / 32;   // 8 warps/block * 4 edges/warp
    for (int hd = 0; hd < HEADS; hd++)
        edge_head_kernel<<<eblocks, 256>>>(src, dst, E, N, hd);

    // 5. finalize
    final_kernel<<<(N * 32 + 255) / 256, 256>>>(out, N);
}

// round 13
// speedup vs baseline: 1.7760x; 1.0847x over previous
#include <cuda_runtime.h>
#include <cuda_bf16.h>
#include <cstdint>

#define MAXN 170000
#define DF   128
#define HEADS 4
#define NEG_SLOPE 0.2f

// -------- scratch (device globals; no allocations allowed) --------
// HEAD-MAJOR layouts: g_h/g_acc = [head][node][32], g_ds/dd/den = [head][node]
__device__ __align__(16) float g_h[MAXN * DF];
__device__ __align__(16) float g_acc[MAXN * DF];
__device__ __align__(16) float g_ds[MAXN * HEADS];
__device__ __align__(16) float g_dd[MAXN * HEADS];
__device__ __align__(16) float g_den[MAXN * HEADS];
// presplit transposed weights: [m][n][k], m=0:W_embed, m=1:W_lin
__device__ __align__(16) __nv_bfloat16 g_Whi[2 * DF * DF];
__device__ __align__(16) __nv_bfloat16 g_Wlo[2 * DF * DF];

// ---------------- zero accumulators -------------------------------
__global__ void zero_kernel(int n) {
    int idx = blockIdx.x * blockDim.x + threadIdx.x;
    int acc4 = n * 32;
    float4 z = make_float4(0.f, 0.f, 0.f, 0.f);
    if (idx < acc4) {
        ((float4*)g_acc)[idx] = z;
    } else if (idx < acc4 + n) {
        ((float4*)g_den)[idx - acc4] = z;
    }
}

// ---------------- W split + transpose (once) ----------------------
__global__ void wsplit_kernel(const float* __restrict__ We,
                              const float* __restrict__ Wl) {
    int idx = blockIdx.x * blockDim.x + threadIdx.x;   // 0..32767
    if (idx >= 2 * DF * DF) return;
    int m = idx >> 14;
    int r = idx & (DF * DF - 1);
    int kk = r >> 7;
    int nn = r & 127;
    float w = (m ? Wl : We)[kk * DF + nn];
    __nv_bfloat16 hi = __float2bfloat16(w);
    g_Whi[m * DF * DF + nn * DF + kk] = hi;
    g_Wlo[m * DF * DF + nn * DF + kk] =
        __float2bfloat16(w - __bfloat162float(hi));
}

// ---------------- bf16-split tensor-core dual GEMM ----------------
// D = A_hi*B_hi + A_hi*B_lo + A_lo*B_hi  (fp32 accum) ~ fp32 accuracy.
// by==0: x @ W_embed -> g_h (HEAD-MAJOR) ; by==1: x @ W_lin (+bias) -> d_out
#define KSTR 40   // padded k-stride in bf16 elems

__device__ __forceinline__ void mma_bf16(float* c, const uint32_t* a,
                                         const uint32_t* b) {
    asm volatile(
        "mma.sync.aligned.m16n8k16.row.col.f32.bf16.bf16.f32 "
        "{%0,%1,%2,%3}, {%4,%5,%6,%7}, {%8,%9}, {%0,%1,%2,%3};\n"
        : "+f"(c[0]), "+f"(c[1]), "+f"(c[2]), "+f"(c[3])
        : "r"(a[0]), "r"(a[1]), "r"(a[2]), "r"(a[3]), "r"(b[0]), "r"(b[1]));
}

__device__ __forceinline__ uint32_t pack2(__nv_bfloat16 a, __nv_bfloat16 b) {
    __nv_bfloat162 t;
    t.x = a; t.y = b;
    return *(uint32_t*)&t;
}

__global__ __launch_bounds__(256, 2)
void gemm_kernel(const float* __restrict__ x,
                 const float* __restrict__ bias,
                 float* __restrict__ lin_out,
                 int N)
{
    __shared__ __nv_bfloat16 As_hi[128 * KSTR];
    __shared__ __nv_bfloat16 As_lo[128 * KSTR];
    __shared__ __nv_bfloat16 Bs_hi[128 * KSTR];   // [n][k]
    __shared__ __nv_bfloat16 Bs_lo[128 * KSTR];

    int by = blockIdx.y;
    const __nv_bfloat16* Wh = g_Whi + by * DF * DF;
    const __nv_bfloat16* Wl = g_Wlo + by * DF * DF;

    int tid = threadIdx.x;
    int warp = tid >> 5;
    int lane = tid & 31;
    int g = lane >> 2;          // 0..7
    int t = lane & 3;           // 0..3
    int wr = warp >> 1;         // 0..3
    int wc = warp & 1;          // 0..1
    int rowBase = blockIdx.x * 128;

    float acc[2][8][4];
    #pragma unroll
    for (int mt = 0; mt < 2; mt++)
        #pragma unroll
        for (int nt = 0; nt < 8; nt++)
            #pragma unroll
            for (int k = 0; k < 4; k++) acc[mt][nt][k] = 0.f;

    int xrow = tid >> 1;                 // 0..127  (also B row)
    int xkq  = (tid & 1) * 16;           // 0 or 16 (also B k-quad)
    int grow = rowBase + xrow;

    for (int kc = 0; kc < DF; kc += 32) {
        // --- A tile: load fp32, split, packed STS.64 ---
        #pragma unroll
        for (int j = 0; j < 4; j++) {
            float4 v = make_float4(0.f, 0.f, 0.f, 0.f);
            if (grow < N) v = *(const float4*)&x[grow * DF + kc + xkq + j * 4];
            int base = xrow * KSTR + xkq + j * 4;
            __nv_bfloat16 h0 = __float2bfloat16(v.x);
            __nv_bfloat16 h1 = __float2bfloat16(v.y);
            __nv_bfloat16 h2 = __float2bfloat16(v.z);
            __nv_bfloat16 h3 = __float2bfloat16(v.w);
            uint2 hv = make_uint2(pack2(h0, h1), pack2(h2, h3));
            *(uint2*)&As_hi[base] = hv;
            uint2 lv = make_uint2(
                pack2(__float2bfloat16(v.x - __bfloat162float(h0)),
                      __float2bfloat16(v.y - __bfloat162float(h1))),
                pack2(__float2bfloat16(v.z - __bfloat162float(h2)),
                      __float2bfloat16(v.w - __bfloat162float(h3))));
            *(uint2*)&As_lo[base] = lv;
        }
        // --- B tile: presplit bf16, LDG.128 -> STS.128 ---
        {
            int goff = xrow * DF + kc + xkq;
            int soff = xrow * KSTR + xkq;
            uint4 bh0 = *(const uint4*)&Wh[goff];
            uint4 bh1 = *(const uint4*)&Wh[goff + 8];
            uint4 bl0 = *(const uint4*)&Wl[goff];
            uint4 bl1 = *(const uint4*)&Wl[goff + 8];
            *(uint4*)&Bs_hi[soff]     = bh0;
            *(uint4*)&Bs_hi[soff + 8] = bh1;
            *(uint4*)&Bs_lo[soff]     = bl0;
            *(uint4*)&Bs_lo[soff + 8] = bl1;
        }
        __syncthreads();

        #pragma unroll
        for (int ks = 0; ks < 32; ks += 16) {
            uint32_t ah[2][4], al[2][4];
            #pragma unroll
            for (int mt = 0; mt < 2; mt++) {
                int m0 = wr * 32 + mt * 16;
                int r0 = (m0 + g) * KSTR + ks + 2 * t;
                int r1 = (m0 + g + 8) * KSTR + ks + 2 * t;
                ah[mt][0] = *(const uint32_t*)&As_hi[r0];
                ah[mt][1] = *(const uint32_t*)&As_hi[r1];
                ah[mt][2] = *(const uint32_t*)&As_hi[r0 + 8];
                ah[mt][3] = *(const uint32_t*)&As_hi[r1 + 8];
                al[mt][0] = *(const uint32_t*)&As_lo[r0];
                al[mt][1] = *(const uint32_t*)&As_lo[r1];
                al[mt][2] = *(const uint32_t*)&As_lo[r0 + 8];
                al[mt][3] = *(const uint32_t*)&As_lo[r1 + 8];
            }
            #pragma unroll
            for (int nt = 0; nt < 8; nt++) {
                int n0 = wc * 64 + nt * 8;
                int bidx = (n0 + g) * KSTR + ks + 2 * t;
                uint32_t bh[2], bl[2];
                bh[0] = *(const uint32_t*)&Bs_hi[bidx];
                bh[1] = *(const uint32_t*)&Bs_hi[bidx + 8];
                bl[0] = *(const uint32_t*)&Bs_lo[bidx];
                bl[1] = *(const uint32_t*)&Bs_lo[bidx + 8];
                #pragma unroll
                for (int mt = 0; mt < 2; mt++) {
                    mma_bf16(acc[mt][nt], ah[mt], bh);   // hi*hi
                    mma_bf16(acc[mt][nt], ah[mt], bl);   // hi*lo
                    mma_bf16(acc[mt][nt], al[mt], bh);   // lo*hi
                }
            }
        }
        __syncthreads();
    }

    // --- epilogue ---
    int N32 = N * 32;
    #pragma unroll
    for (int nt = 0; nt < 8; nt++) {
        int col = wc * 64 + nt * 8 + 2 * t;
        float b0 = 0.f, b1 = 0.f;
        if (by) { b0 = bias[col]; b1 = bias[col + 1]; }
        int hd = col >> 5;
        int ch = col & 31;
        #pragma unroll
        for (int mt = 0; mt < 2; mt++) {
            int r0 = rowBase + wr * 32 + mt * 16 + g;
            if (r0 < N) {
                float2 o = make_float2(acc[mt][nt][0] + b0, acc[mt][nt][1] + b1);
                if (by) *(float2*)&lin_out[r0 * DF + col] = o;
                else    *(float2*)&g_h[hd * N32 + r0 * 32 + ch] = o;
            }
            int r1 = r0 + 8;
            if (r1 < N) {
                float2 o = make_float2(acc[mt][nt][2] + b0, acc[mt][nt][3] + b1);
                if (by) *(float2*)&lin_out[r1 * DF + col] = o;
                else    *(float2*)&g_h[hd * N32 + r1 * 32 + ch] = o;
            }
        }
    }
}

// ---------------- per-node attention dots (head-major h) ----------
__global__ void dot_kernel(const float* __restrict__ a_src,
                           const float* __restrict__ a_dst,
                           int N)
{
    int n = (blockIdx.x * blockDim.x + threadIdx.x) >> 5;
    int lane = threadIdx.x & 31;
    if (n >= N) return;
    int hd = lane >> 3;
    int lg = lane & 7;

    float4 hv = *(const float4*)&g_h[hd * (N * 32) + n * 32 + lg * 4];
    float4 as = ((const float4*)a_src)[lane];
    float4 ad = ((const float4*)a_dst)[lane];

    float ps = hv.x * as.x + hv.y * as.y + hv.z * as.z + hv.w * as.w;
    float pd = hv.x * ad.x + hv.y * ad.y + hv.z * ad.z + hv.w * ad.w;

    ps += __shfl_xor_sync(0xffffffffu, ps, 1);
    ps += __shfl_xor_sync(0xffffffffu, ps, 2);
    ps += __shfl_xor_sync(0xffffffffu, ps, 4);
    pd += __shfl_xor_sync(0xffffffffu, pd, 1);
    pd += __shfl_xor_sync(0xffffffffu, pd, 2);
    pd += __shfl_xor_sync(0xffffffffu, pd, 4);

    if (lg == 0) {
        g_ds[hd * N + n] = ps;
        g_dd[hd * N + n] = pd;
    }
}

// ---------------- per-head edge pass (16 edges/warp, MLP=4) -------
// 8 lanes per edge (one 128B line per gather/red). Lanes 0..15 preload
// all 16 edges' scalars; gathers for 4 edges issued back-to-back.
__global__ void edge_head_kernel(const int* __restrict__ src,
                                 const int* __restrict__ dst,
                                 int E, int N, int hd)
{
    int warpId = (blockIdx.x * blockDim.x + threadIdx.x) >> 5;
    int lane = threadIdx.x & 31;
    int base = warpId * 16;
    if (base >= E) return;
    int sub = lane >> 3;
    int lg  = lane & 7;

    // lanes 0..15 compute scalars for edges base+lane
    int eL = base + lane;
    int sL = 0, dL = 0;
    float wL = 0.f;
    if (lane < 16 && eL < E) {
        sL = __ldg(&src[eL]);
        dL = __ldg(&dst[eL]);
        float z = __ldg(&g_ds[hd * N + sL]) + __ldg(&g_dd[hd * N + dL]);
        z = (z >= 0.f) ? z : NEG_SLOPE * z;
        wL = __expf(z);
    }

    int N32 = N * 32;
    float4 v[4];
    int   dd[4];
    float ww[4];
    bool  act[4];
    #pragma unroll
    for (int it = 0; it < 4; it++) {
        int e = base + it * 4 + sub;
        act[it] = (e < E);
        int s  = __shfl_sync(0xffffffffu, sL, it * 4 + sub);
        dd[it] = __shfl_sync(0xffffffffu, dL, it * 4 + sub);
        ww[it] = __shfl_sync(0xffffffffu, wL, it * 4 + sub);
        v[it] = make_float4(0.f, 0.f, 0.f, 0.f);
        if (act[it]) v[it] = *(const float4*)&g_h[hd * N32 + s * 32 + lg * 4];
    }
    #pragma unroll
    for (int it = 0; it < 4; it++) {
        if (act[it]) {
            float w = ww[it];
            int d = dd[it];
            if (lg == 0)
                atomicAdd(&g_den[hd * N + d], w);
            float a0 = w * v[it].x, a1 = w * v[it].y;
            float a2 = w * v[it].z, a3 = w * v[it].w;
            float* p = &g_acc[hd * N32 + d * 32 + lg * 4];
            asm volatile("red.global.add.v4.f32 [%0], {%1, %2, %3, %4};"
                         :: "l"(p), "f"(a0), "f"(a1), "f"(a2), "f"(a3)
                         : "memory");
        }
    }
}

// ---------------- finalize (head-major acc -> row-major out) ------
__global__ void final_kernel(float* __restrict__ out, int N)
{
    int idx = blockIdx.x * blockDim.x + threadIdx.x;   // float4 index over N*32
    if (idx >= N * 32) return;
    int n = idx >> 5;
    int q = idx & 31;
    int hd = q >> 3;
    int j  = q & 7;
    float den = g_den[hd * N + n];
    float inv = (den > 0.f) ? (1.0f / den) : 0.f;
    float4 a = ((const float4*)g_acc)[hd * (N * 8) + n * 8 + j];
    float4 o = ((float4*)out)[idx];
    o.x += a.x * inv;
    o.y += a.y * inv;
    o.z += a.z * inv;
    o.w += a.w * inv;
    ((float4*)out)[idx] = o;
}

// ------------------------------------------------------------------
extern "C" void kernel_launch(void* const* d_in, const int* in_sizes, int n_in,
                              void* d_out, int out_size)
{
    const float* x       = (const float*)d_in[0];
    const float* W_embed = (const float*)d_in[1];
    const float* a_src   = (const float*)d_in[2];
    const float* a_dst   = (const float*)d_in[3];
    const float* W_lin   = (const float*)d_in[4];
    const float* bias    = (const float*)d_in[5];
    const int*   src     = (const int*)d_in[6];
    const int*   dst     = (const int*)d_in[7];
    float* out = (float*)d_out;

    int N = in_sizes[0] / DF;
    int E = in_sizes[6];

    // 0. presplit weights (tiny)
    wsplit_kernel<<<(2 * DF * DF + 255) / 256, 256>>>(W_embed, W_lin);

    // 1. zero accumulators
    int z4 = N * 33;
    zero_kernel<<<(z4 + 255) / 256, 256>>>(N);

    // 2. bf16-split tensor dual GEMM: h -> g_h (head-major), lin+bias -> d_out
    dim3 ggrid((N + 127) / 128, 2);
    gemm_kernel<<<ggrid, 256>>>(x, bias, out, N);

    // 3. attention dots
    dot_kernel<<<(N + 7) / 8, 256>>>(a_src, a_dst, N);

    // 4. edge passes, one head at a time (L2-resident working set)
    int eblocks = (E + 127) / 128;   // 8 warps/block * 16 edges/warp
    for (int hd = 0; hd < HEADS; hd++)
        edge_head_kernel<<<eblocks, 256>>>(src, dst, E, N, hd);

    // 5. finalize
    final_kernel<<<(N * 32 + 255) / 256, 256>>>(out, N);
}

// round 14
// speedup vs baseline: 1.7775x; 1.0008x over previous
#include <cuda_runtime.h>
#include <cuda_bf16.h>
#include <cstdint>

#define MAXN 170000
#define DF   128
#define HEADS 4
#define NEG_SLOPE 0.2f

// -------- scratch (device globals; no allocations allowed) --------
// HEAD-MAJOR layouts: g_h/g_acc = [head][node][32], g_ds/dd/den = [head][node]
// g_acc / g_den are zero at kernel_launch entry: zero-initialized at load,
// re-zeroed by final_kernel after consumption (invariant across graph replays).
__device__ __align__(16) float g_h[MAXN * DF];
__device__ __align__(16) float g_acc[MAXN * DF];
__device__ __align__(16) float g_ds[MAXN * HEADS];
__device__ __align__(16) float g_dd[MAXN * HEADS];
__device__ __align__(16) float g_den[MAXN * HEADS];
// presplit transposed weights: [m][n][k], m=0:W_embed, m=1:W_lin
__device__ __align__(16) __nv_bfloat16 g_Whi[2 * DF * DF];
__device__ __align__(16) __nv_bfloat16 g_Wlo[2 * DF * DF];

// ---------------- W split + transpose (once per call) -------------
__global__ void wsplit_kernel(const float* __restrict__ We,
                              const float* __restrict__ Wl) {
    int idx = blockIdx.x * blockDim.x + threadIdx.x;   // 0..32767
    if (idx >= 2 * DF * DF) return;
    int m = idx >> 14;
    int r = idx & (DF * DF - 1);
    int kk = r >> 7;
    int nn = r & 127;
    float w = (m ? Wl : We)[kk * DF + nn];
    __nv_bfloat16 hi = __float2bfloat16(w);
    g_Whi[m * DF * DF + nn * DF + kk] = hi;
    g_Wlo[m * DF * DF + nn * DF + kk] =
        __float2bfloat16(w - __bfloat162float(hi));
}

// ---------------- bf16-split tensor-core dual GEMM ----------------
// D = A_hi*B_hi + A_hi*B_lo + A_lo*B_hi  (fp32 accum) ~ fp32 accuracy.
// by==0: x @ W_embed -> g_h (HEAD-MAJOR) ; by==1: x @ W_lin (+bias) -> d_out
#define KSTR 40   // padded k-stride in bf16 elems

__device__ __forceinline__ void mma_bf16(float* c, const uint32_t* a,
                                         const uint32_t* b) {
    asm volatile(
        "mma.sync.aligned.m16n8k16.row.col.f32.bf16.bf16.f32 "
        "{%0,%1,%2,%3}, {%4,%5,%6,%7}, {%8,%9}, {%0,%1,%2,%3};\n"
        : "+f"(c[0]), "+f"(c[1]), "+f"(c[2]), "+f"(c[3])
        : "r"(a[0]), "r"(a[1]), "r"(a[2]), "r"(a[3]), "r"(b[0]), "r"(b[1]));
}

__device__ __forceinline__ uint32_t pack2(__nv_bfloat16 a, __nv_bfloat16 b) {
    __nv_bfloat162 t;
    t.x = a; t.y = b;
    return *(uint32_t*)&t;
}

__global__ __launch_bounds__(256, 2)
void gemm_kernel(const float* __restrict__ x,
                 const float* __restrict__ bias,
                 float* __restrict__ lin_out,
                 int N)
{
    __shared__ __nv_bfloat16 As_hi[128 * KSTR];
    __shared__ __nv_bfloat16 As_lo[128 * KSTR];
    __shared__ __nv_bfloat16 Bs_hi[128 * KSTR];   // [n][k]
    __shared__ __nv_bfloat16 Bs_lo[128 * KSTR];

    int by = blockIdx.y;
    const __nv_bfloat16* Wh = g_Whi + by * DF * DF;
    const __nv_bfloat16* Wl = g_Wlo + by * DF * DF;

    int tid = threadIdx.x;
    int warp = tid >> 5;
    int lane = tid & 31;
    int g = lane >> 2;          // 0..7
    int t = lane & 3;           // 0..3
    int wr = warp >> 1;         // 0..3
    int wc = warp & 1;          // 0..1
    int rowBase = blockIdx.x * 128;

    float acc[2][8][4];
    #pragma unroll
    for (int mt = 0; mt < 2; mt++)
        #pragma unroll
        for (int nt = 0; nt < 8; nt++)
            #pragma unroll
            for (int k = 0; k < 4; k++) acc[mt][nt][k] = 0.f;

    int xrow = tid >> 1;                 // 0..127  (also B row)
    int xkq  = (tid & 1) * 16;           // 0 or 16 (also B k-quad)
    int grow = rowBase + xrow;

    for (int kc = 0; kc < DF; kc += 32) {
        // --- A tile: load fp32, split, packed STS.64 ---
        #pragma unroll
        for (int j = 0; j < 4; j++) {
            float4 v = make_float4(0.f, 0.f, 0.f, 0.f);
            if (grow < N) v = *(const float4*)&x[grow * DF + kc + xkq + j * 4];
            int base = xrow * KSTR + xkq + j * 4;
            __nv_bfloat16 h0 = __float2bfloat16(v.x);
            __nv_bfloat16 h1 = __float2bfloat16(v.y);
            __nv_bfloat16 h2 = __float2bfloat16(v.z);
            __nv_bfloat16 h3 = __float2bfloat16(v.w);
            uint2 hv = make_uint2(pack2(h0, h1), pack2(h2, h3));
            *(uint2*)&As_hi[base] = hv;
            uint2 lv = make_uint2(
                pack2(__float2bfloat16(v.x - __bfloat162float(h0)),
                      __float2bfloat16(v.y - __bfloat162float(h1))),
                pack2(__float2bfloat16(v.z - __bfloat162float(h2)),
                      __float2bfloat16(v.w - __bfloat162float(h3))));
            *(uint2*)&As_lo[base] = lv;
        }
        // --- B tile: presplit bf16, LDG.128 -> STS.128 ---
        {
            int goff = xrow * DF + kc + xkq;
            int soff = xrow * KSTR + xkq;
            uint4 bh0 = *(const uint4*)&Wh[goff];
            uint4 bh1 = *(const uint4*)&Wh[goff + 8];
            uint4 bl0 = *(const uint4*)&Wl[goff];
            uint4 bl1 = *(const uint4*)&Wl[goff + 8];
            *(uint4*)&Bs_hi[soff]     = bh0;
            *(uint4*)&Bs_hi[soff + 8] = bh1;
            *(uint4*)&Bs_lo[soff]     = bl0;
            *(uint4*)&Bs_lo[soff + 8] = bl1;
        }
        __syncthreads();

        #pragma unroll
        for (int ks = 0; ks < 32; ks += 16) {
            uint32_t ah[2][4], al[2][4];
            #pragma unroll
            for (int mt = 0; mt < 2; mt++) {
                int m0 = wr * 32 + mt * 16;
                int r0 = (m0 + g) * KSTR + ks + 2 * t;
                int r1 = (m0 + g + 8) * KSTR + ks + 2 * t;
                ah[mt][0] = *(const uint32_t*)&As_hi[r0];
                ah[mt][1] = *(const uint32_t*)&As_hi[r1];
                ah[mt][2] = *(const uint32_t*)&As_hi[r0 + 8];
                ah[mt][3] = *(const uint32_t*)&As_hi[r1 + 8];
                al[mt][0] = *(const uint32_t*)&As_lo[r0];
                al[mt][1] = *(const uint32_t*)&As_lo[r1];
                al[mt][2] = *(const uint32_t*)&As_lo[r0 + 8];
                al[mt][3] = *(const uint32_t*)&As_lo[r1 + 8];
            }
            #pragma unroll
            for (int nt = 0; nt < 8; nt++) {
                int n0 = wc * 64 + nt * 8;
                int bidx = (n0 + g) * KSTR + ks + 2 * t;
                uint32_t bh[2], bl[2];
                bh[0] = *(const uint32_t*)&Bs_hi[bidx];
                bh[1] = *(const uint32_t*)&Bs_hi[bidx + 8];
                bl[0] = *(const uint32_t*)&Bs_lo[bidx];
                bl[1] = *(const uint32_t*)&Bs_lo[bidx + 8];
                #pragma unroll
                for (int mt = 0; mt < 2; mt++) {
                    mma_bf16(acc[mt][nt], ah[mt], bh);   // hi*hi
                    mma_bf16(acc[mt][nt], ah[mt], bl);   // hi*lo
                    mma_bf16(acc[mt][nt], al[mt], bh);   // lo*hi
                }
            }
        }
        __syncthreads();
    }

    // --- epilogue ---
    int N32 = N * 32;
    #pragma unroll
    for (int nt = 0; nt < 8; nt++) {
        int col = wc * 64 + nt * 8 + 2 * t;
        float b0 = 0.f, b1 = 0.f;
        if (by) { b0 = bias[col]; b1 = bias[col + 1]; }
        int hd = col >> 5;
        int ch = col & 31;
        #pragma unroll
        for (int mt = 0; mt < 2; mt++) {
            int r0 = rowBase + wr * 32 + mt * 16 + g;
            if (r0 < N) {
                float2 o = make_float2(acc[mt][nt][0] + b0, acc[mt][nt][1] + b1);
                if (by) *(float2*)&lin_out[r0 * DF + col] = o;
                else    *(float2*)&g_h[hd * N32 + r0 * 32 + ch] = o;
            }
            int r1 = r0 + 8;
            if (r1 < N) {
                float2 o = make_float2(acc[mt][nt][2] + b0, acc[mt][nt][3] + b1);
                if (by) *(float2*)&lin_out[r1 * DF + col] = o;
                else    *(float2*)&g_h[hd * N32 + r1 * 32 + ch] = o;
            }
        }
    }
}

// ---------------- per-node attention dots (head-major h) ----------
__global__ void dot_kernel(const float* __restrict__ a_src,
                           const float* __restrict__ a_dst,
                           int N)
{
    int n = (blockIdx.x * blockDim.x + threadIdx.x) >> 5;
    int lane = threadIdx.x & 31;
    if (n >= N) return;
    int hd = lane >> 3;
    int lg = lane & 7;

    float4 hv = *(const float4*)&g_h[hd * (N * 32) + n * 32 + lg * 4];
    float4 as = ((const float4*)a_src)[lane];
    float4 ad = ((const float4*)a_dst)[lane];

    float ps = hv.x * as.x + hv.y * as.y + hv.z * as.z + hv.w * as.w;
    float pd = hv.x * ad.x + hv.y * ad.y + hv.z * ad.z + hv.w * ad.w;

    ps += __shfl_xor_sync(0xffffffffu, ps, 1);
    ps += __shfl_xor_sync(0xffffffffu, ps, 2);
    ps += __shfl_xor_sync(0xffffffffu, ps, 4);
    pd += __shfl_xor_sync(0xffffffffu, pd, 1);
    pd += __shfl_xor_sync(0xffffffffu, pd, 2);
    pd += __shfl_xor_sync(0xffffffffu, pd, 4);

    if (lg == 0) {
        g_ds[hd * N + n] = ps;
        g_dd[hd * N + n] = pd;
    }
}

// ---------------- per-head edge pass (32 edges/warp, MLP=8) -------
// 8 lanes per edge (one 128B line per gather/red). Every lane preloads
// one edge's scalars; gathers for 8 edges issued back-to-back.
__global__ void edge_head_kernel(const int* __restrict__ src,
                                 const int* __restrict__ dst,
                                 int E, int N, int hd)
{
    int warpId = (blockIdx.x * blockDim.x + threadIdx.x) >> 5;
    int lane = threadIdx.x & 31;
    int base = warpId * 32;
    if (base >= E) return;
    int sub = lane >> 3;
    int lg  = lane & 7;

    // every lane computes scalars for edge base+lane
    int eL = base + lane;
    int sL = 0, dL = 0;
    float wL = 0.f;
    if (eL < E) {
        sL = __ldg(&src[eL]);
        dL = __ldg(&dst[eL]);
        float z = __ldg(&g_ds[hd * N + sL]) + __ldg(&g_dd[hd * N + dL]);
        z = (z >= 0.f) ? z : NEG_SLOPE * z;
        wL = __expf(z);
    }

    int N32 = N * 32;
    float4 v[8];
    int   dd[8];
    float ww[8];
    bool  act[8];
    #pragma unroll
    for (int it = 0; it < 8; it++) {
        int e = base + it * 4 + sub;
        act[it] = (e < E);
        int s  = __shfl_sync(0xffffffffu, sL, it * 4 + sub);
        dd[it] = __shfl_sync(0xffffffffu, dL, it * 4 + sub);
        ww[it] = __shfl_sync(0xffffffffu, wL, it * 4 + sub);
        v[it] = make_float4(0.f, 0.f, 0.f, 0.f);
        if (act[it]) v[it] = *(const float4*)&g_h[hd * N32 + s * 32 + lg * 4];
    }
    #pragma unroll
    for (int it = 0; it < 8; it++) {
        if (act[it]) {
            float w = ww[it];
            int d = dd[it];
            if (lg == 0)
                atomicAdd(&g_den[hd * N + d], w);
            float a0 = w * v[it].x, a1 = w * v[it].y;
            float a2 = w * v[it].z, a3 = w * v[it].w;
            float* p = &g_acc[hd * N32 + d * 32 + lg * 4];
            asm volatile("red.global.add.v4.f32 [%0], {%1, %2, %3, %4};"
                         :: "l"(p), "f"(a0), "f"(a1), "f"(a2), "f"(a3)
                         : "memory");
        }
    }
}

// ---------------- finalize + scratch re-zero ----------------------
// out += acc/den (head-major acc -> row-major out); then restore the
// "acc/den are zero" invariant for the next kernel_launch/graph replay.
__global__ void final_kernel(float* __restrict__ out, int N)
{
    int idx = blockIdx.x * blockDim.x + threadIdx.x;   // float4 index over N*32
    if (idx >= N * 32) return;
    int n = idx >> 5;
    int q = idx & 31;
    int hd = q >> 3;
    int j  = q & 7;
    float den = g_den[hd * N + n];
    float inv = (den > 0.f) ? (1.0f / den) : 0.f;
    int aidx = hd * (N * 8) + n * 8 + j;
    float4 a = ((const float4*)g_acc)[aidx];
    float4 o = ((float4*)out)[idx];
    o.x += a.x * inv;
    o.y += a.y * inv;
    o.z += a.z * inv;
    o.w += a.w * inv;
    ((float4*)out)[idx] = o;
    // re-zero scratch for next invocation
    ((float4*)g_acc)[aidx] = make_float4(0.f, 0.f, 0.f, 0.f);
    if (j == 0 && (q & 7) == 0)
        ;   // (den zero handled below by designated thread)
    if ((q & 7) == 0 && j == 0)
        ;
    if (j == 0)
        g_den[hd * N + n] = 0.f;   // 8x redundant-free: only j==0 writes
}

// ------------------------------------------------------------------
extern "C" void kernel_launch(void* const* d_in, const int* in_sizes, int n_in,
                              void* d_out, int out_size)
{
    const float* x       = (const float*)d_in[0];
    const float* W_embed = (const float*)d_in[1];
    const float* a_src   = (const float*)d_in[2];
    const float* a_dst   = (const float*)d_in[3];
    const float* W_lin   = (const float*)d_in[4];
    const float* bias    = (const float*)d_in[5];
    const int*   src     = (const int*)d_in[6];
    const int*   dst     = (const int*)d_in[7];
    float* out = (float*)d_out;

    int N = in_sizes[0] / DF;
    int E = in_sizes[6];

    // 0. presplit weights (tiny)
    wsplit_kernel<<<(2 * DF * DF + 255) / 256, 256>>>(W_embed, W_lin);

    // 1. bf16-split tensor dual GEMM: h -> g_h (head-major), lin+bias -> d_out
    dim3 ggrid((N + 127) / 128, 2);
    gemm_kernel<<<ggrid, 256>>>(x, bias, out, N);

    // 2. attention dots
    dot_kernel<<<(N + 7) / 8, 256>>>(a_src, a_dst, N);

    // 3. edge passes, one head at a time (L2-resident working set)
    int eblocks = (E + 255) / 256;   // 8 warps/block * 32 edges/warp
    for (int hd = 0; hd < HEADS; hd++)
        edge_head_kernel<<<eblocks, 256>>>(src, dst, E, N, hd);

    // 4. finalize + re-zero scratch (acc/den zero-invariant across calls)
    final_kernel<<<(N * 32 + 255) / 256, 256>>>(out, N);
}

// round 15
// speedup vs baseline: 1.8135x; 1.0203x over previous
#include <cuda_runtime.h>
#include <cuda_bf16.h>
#include <cstdint>

#define MAXN 170000
#define DF   128
#define HEADS 4
#define NEG_SLOPE 0.2f

// -------- scratch (device globals; no allocations allowed) --------
// HEAD-MAJOR layouts: g_h/g_acc = [head][node][32], g_ds/dd/den = [head][node]
// g_acc / g_den are zero at kernel_launch entry: zero-initialized at load,
// re-zeroed by final_kernel after consumption (invariant across graph replays).
__device__ __align__(16) float g_h[MAXN * DF];
__device__ __align__(16) float g_acc[MAXN * DF];
__device__ __align__(16) float g_ds[MAXN * HEADS];
__device__ __align__(16) float g_dd[MAXN * HEADS];
__device__ __align__(16) float g_den[MAXN * HEADS];
// presplit transposed weights: [m][n][k], m=0:W_embed, m=1:W_lin
__device__ __align__(16) __nv_bfloat16 g_Whi[2 * DF * DF];
__device__ __align__(16) __nv_bfloat16 g_Wlo[2 * DF * DF];

// ---------------- W split + transpose (once per call) -------------
__global__ void wsplit_kernel(const float* __restrict__ We,
                              const float* __restrict__ Wl) {
    int idx = blockIdx.x * blockDim.x + threadIdx.x;   // 0..32767
    if (idx >= 2 * DF * DF) return;
    int m = idx >> 14;
    int r = idx & (DF * DF - 1);
    int kk = r >> 7;
    int nn = r & 127;
    float w = (m ? Wl : We)[kk * DF + nn];
    __nv_bfloat16 hi = __float2bfloat16(w);
    g_Whi[m * DF * DF + nn * DF + kk] = hi;
    g_Wlo[m * DF * DF + nn * DF + kk] =
        __float2bfloat16(w - __bfloat162float(hi));
}

// ---------------- bf16-split tensor-core dual GEMM ----------------
// D = A_hi*B_hi + A_hi*B_lo + A_lo*B_hi  (fp32 accum) ~ fp32 accuracy.
// by==0: x @ W_embed -> g_h (HEAD-MAJOR) ; by==1: x @ W_lin (+bias) -> d_out
#define KSTR 40   // padded k-stride in bf16 elems

__device__ __forceinline__ void mma_bf16(float* c, const uint32_t* a,
                                         const uint32_t* b) {
    asm volatile(
        "mma.sync.aligned.m16n8k16.row.col.f32.bf16.bf16.f32 "
        "{%0,%1,%2,%3}, {%4,%5,%6,%7}, {%8,%9}, {%0,%1,%2,%3};\n"
        : "+f"(c[0]), "+f"(c[1]), "+f"(c[2]), "+f"(c[3])
        : "r"(a[0]), "r"(a[1]), "r"(a[2]), "r"(a[3]), "r"(b[0]), "r"(b[1]));
}

__device__ __forceinline__ uint32_t pack2(__nv_bfloat16 a, __nv_bfloat16 b) {
    __nv_bfloat162 t;
    t.x = a; t.y = b;
    return *(uint32_t*)&t;
}

__global__ __launch_bounds__(256, 2)
void gemm_kernel(const float* __restrict__ x,
                 const float* __restrict__ bias,
                 float* __restrict__ lin_out,
                 int N)
{
    __shared__ __nv_bfloat16 As_hi[128 * KSTR];
    __shared__ __nv_bfloat16 As_lo[128 * KSTR];
    __shared__ __nv_bfloat16 Bs_hi[128 * KSTR];   // [n][k]
    __shared__ __nv_bfloat16 Bs_lo[128 * KSTR];

    int by = blockIdx.y;
    const __nv_bfloat16* Wh = g_Whi + by * DF * DF;
    const __nv_bfloat16* Wl = g_Wlo + by * DF * DF;

    int tid = threadIdx.x;
    int warp = tid >> 5;
    int lane = tid & 31;
    int g = lane >> 2;          // 0..7
    int t = lane & 3;           // 0..3
    int wr = warp >> 1;         // 0..3
    int wc = warp & 1;          // 0..1
    int rowBase = blockIdx.x * 128;

    float acc[2][8][4];
    #pragma unroll
    for (int mt = 0; mt < 2; mt++)
        #pragma unroll
        for (int nt = 0; nt < 8; nt++)
            #pragma unroll
            for (int k = 0; k < 4; k++) acc[mt][nt][k] = 0.f;

    int xrow = tid >> 1;                 // 0..127  (also B row)
    int xkq  = (tid & 1) * 16;           // 0 or 16 (also B k-quad)
    int grow = rowBase + xrow;

    for (int kc = 0; kc < DF; kc += 32) {
        // --- A tile: load fp32, split, packed STS.64 ---
        #pragma unroll
        for (int j = 0; j < 4; j++) {
            float4 v = make_float4(0.f, 0.f, 0.f, 0.f);
            if (grow < N) v = *(const float4*)&x[grow * DF + kc + xkq + j * 4];
            int base = xrow * KSTR + xkq + j * 4;
            __nv_bfloat16 h0 = __float2bfloat16(v.x);
            __nv_bfloat16 h1 = __float2bfloat16(v.y);
            __nv_bfloat16 h2 = __float2bfloat16(v.z);
            __nv_bfloat16 h3 = __float2bfloat16(v.w);
            uint2 hv = make_uint2(pack2(h0, h1), pack2(h2, h3));
            *(uint2*)&As_hi[base] = hv;
            uint2 lv = make_uint2(
                pack2(__float2bfloat16(v.x - __bfloat162float(h0)),
                      __float2bfloat16(v.y - __bfloat162float(h1))),
                pack2(__float2bfloat16(v.z - __bfloat162float(h2)),
                      __float2bfloat16(v.w - __bfloat162float(h3))));
            *(uint2*)&As_lo[base] = lv;
        }
        // --- B tile: presplit bf16, LDG.128 -> STS.128 ---
        {
            int goff = xrow * DF + kc + xkq;
            int soff = xrow * KSTR + xkq;
            uint4 bh0 = *(const uint4*)&Wh[goff];
            uint4 bh1 = *(const uint4*)&Wh[goff + 8];
            uint4 bl0 = *(const uint4*)&Wl[goff];
            uint4 bl1 = *(const uint4*)&Wl[goff + 8];
            *(uint4*)&Bs_hi[soff]     = bh0;
            *(uint4*)&Bs_hi[soff + 8] = bh1;
            *(uint4*)&Bs_lo[soff]     = bl0;
            *(uint4*)&Bs_lo[soff + 8] = bl1;
        }
        __syncthreads();

        #pragma unroll
        for (int ks = 0; ks < 32; ks += 16) {
            uint32_t ah[2][4], al[2][4];
            #pragma unroll
            for (int mt = 0; mt < 2; mt++) {
                int m0 = wr * 32 + mt * 16;
                int r0 = (m0 + g) * KSTR + ks + 2 * t;
                int r1 = (m0 + g + 8) * KSTR + ks + 2 * t;
                ah[mt][0] = *(const uint32_t*)&As_hi[r0];
                ah[mt][1] = *(const uint32_t*)&As_hi[r1];
                ah[mt][2] = *(const uint32_t*)&As_hi[r0 + 8];
                ah[mt][3] = *(const uint32_t*)&As_hi[r1 + 8];
                al[mt][0] = *(const uint32_t*)&As_lo[r0];
                al[mt][1] = *(const uint32_t*)&As_lo[r1];
                al[mt][2] = *(const uint32_t*)&As_lo[r0 + 8];
                al[mt][3] = *(const uint32_t*)&As_lo[r1 + 8];
            }
            #pragma unroll
            for (int nt = 0; nt < 8; nt++) {
                int n0 = wc * 64 + nt * 8;
                int bidx = (n0 + g) * KSTR + ks + 2 * t;
                uint32_t bh[2], bl[2];
                bh[0] = *(const uint32_t*)&Bs_hi[bidx];
                bh[1] = *(const uint32_t*)&Bs_hi[bidx + 8];
                bl[0] = *(const uint32_t*)&Bs_lo[bidx];
                bl[1] = *(const uint32_t*)&Bs_lo[bidx + 8];
                #pragma unroll
                for (int mt = 0; mt < 2; mt++) {
                    mma_bf16(acc[mt][nt], ah[mt], bh);   // hi*hi
                    mma_bf16(acc[mt][nt], ah[mt], bl);   // hi*lo
                    mma_bf16(acc[mt][nt], al[mt], bh);   // lo*hi
                }
            }
        }
        __syncthreads();
    }

    // --- epilogue ---
    int N32 = N * 32;
    #pragma unroll
    for (int nt = 0; nt < 8; nt++) {
        int col = wc * 64 + nt * 8 + 2 * t;
        float b0 = 0.f, b1 = 0.f;
        if (by) { b0 = bias[col]; b1 = bias[col + 1]; }
        int hd = col >> 5;
        int ch = col & 31;
        #pragma unroll
        for (int mt = 0; mt < 2; mt++) {
            int r0 = rowBase + wr * 32 + mt * 16 + g;
            if (r0 < N) {
                float2 o = make_float2(acc[mt][nt][0] + b0, acc[mt][nt][1] + b1);
                if (by) *(float2*)&lin_out[r0 * DF + col] = o;
                else    *(float2*)&g_h[hd * N32 + r0 * 32 + ch] = o;
            }
            int r1 = r0 + 8;
            if (r1 < N) {
                float2 o = make_float2(acc[mt][nt][2] + b0, acc[mt][nt][3] + b1);
                if (by) *(float2*)&lin_out[r1 * DF + col] = o;
                else    *(float2*)&g_h[hd * N32 + r1 * 32 + ch] = o;
            }
        }
    }
}

// ---------------- per-node attention dots (head-major h) ----------
__global__ void dot_kernel(const float* __restrict__ a_src,
                           const float* __restrict__ a_dst,
                           int N)
{
    int n = (blockIdx.x * blockDim.x + threadIdx.x) >> 5;
    int lane = threadIdx.x & 31;
    if (n >= N) return;
    int hd = lane >> 3;
    int lg = lane & 7;

    float4 hv = *(const float4*)&g_h[hd * (N * 32) + n * 32 + lg * 4];
    float4 as = ((const float4*)a_src)[lane];
    float4 ad = ((const float4*)a_dst)[lane];

    float ps = hv.x * as.x + hv.y * as.y + hv.z * as.z + hv.w * as.w;
    float pd = hv.x * ad.x + hv.y * ad.y + hv.z * ad.z + hv.w * ad.w;

    ps += __shfl_xor_sync(0xffffffffu, ps, 1);
    ps += __shfl_xor_sync(0xffffffffu, ps, 2);
    ps += __shfl_xor_sync(0xffffffffu, ps, 4);
    pd += __shfl_xor_sync(0xffffffffu, pd, 1);
    pd += __shfl_xor_sync(0xffffffffu, pd, 2);
    pd += __shfl_xor_sync(0xffffffffu, pd, 4);

    if (lg == 0) {
        g_ds[hd * N + n] = ps;
        g_dd[hd * N + n] = pd;
    }
}

// ---------------- per-head edge pass ------------------------------
// 32 edges/warp, 2 batches of 4 buffered gathers (MLP=4, low regs).
// 8 lanes per edge: one 128B line per gather/red. Scalars held
// 1-edge-per-lane; shfl-broadcast to the 8-lane groups.
__global__ __launch_bounds__(256, 6)
void edge_head_kernel(const int* __restrict__ src,
                      const int* __restrict__ dst,
                      int E, int N, int hd)
{
    int warpId = (blockIdx.x * blockDim.x + threadIdx.x) >> 5;
    int lane = threadIdx.x & 31;
    int base = warpId * 32;
    if (base >= E) return;
    int sub = lane >> 3;
    int lg  = lane & 7;

    // every lane computes scalars for edge base+lane
    int eL = base + lane;
    int sL = 0, dL = 0;
    float wL = 0.f;
    if (eL < E) {
        sL = __ldg(&src[eL]);
        dL = __ldg(&dst[eL]);
        float z = __ldg(&g_ds[hd * N + sL]) + __ldg(&g_dd[hd * N + dL]);
        z = (z >= 0.f) ? z : NEG_SLOPE * z;
        wL = __expf(z);
    }

    int N32 = N * 32;
    #pragma unroll
    for (int half = 0; half < 2; half++) {
        float4 v[4];
        int   dd[4];
        float ww[4];
        bool  act[4];
        #pragma unroll
        for (int it = 0; it < 4; it++) {
            int ln = half * 16 + it * 4 + sub;
            int e = base + ln;
            act[it] = (e < E);
            int s  = __shfl_sync(0xffffffffu, sL, ln);
            dd[it] = __shfl_sync(0xffffffffu, dL, ln);
            ww[it] = __shfl_sync(0xffffffffu, wL, ln);
            v[it] = make_float4(0.f, 0.f, 0.f, 0.f);
            if (act[it])
                v[it] = *(const float4*)&g_h[hd * N32 + s * 32 + lg * 4];
        }
        #pragma unroll
        for (int it = 0; it < 4; it++) {
            if (act[it]) {
                float w = ww[it];
                int d = dd[it];
                if (lg == 0)
                    atomicAdd(&g_den[hd * N + d], w);
                float a0 = w * v[it].x, a1 = w * v[it].y;
                float a2 = w * v[it].z, a3 = w * v[it].w;
                float* p = &g_acc[hd * N32 + d * 32 + lg * 4];
                asm volatile("red.global.add.v4.f32 [%0], {%1, %2, %3, %4};"
                             :: "l"(p), "f"(a0), "f"(a1), "f"(a2), "f"(a3)
                             : "memory");
            }
        }
    }
}

// ---------------- finalize + scratch re-zero ----------------------
// out += acc/den (head-major acc -> row-major out); then restore the
// "acc/den are zero" invariant for the next kernel_launch/graph replay.
__global__ void final_kernel(float* __restrict__ out, int N)
{
    int idx = blockIdx.x * blockDim.x + threadIdx.x;   // float4 index over N*32
    if (idx >= N * 32) return;
    int n = idx >> 5;
    int q = idx & 31;
    int hd = q >> 3;
    int j  = q & 7;
    float den = g_den[hd * N + n];
    float inv = (den > 0.f) ? (1.0f / den) : 0.f;
    int aidx = hd * (N * 8) + n * 8 + j;
    float4 a = ((const float4*)g_acc)[aidx];
    float4 o = ((float4*)out)[idx];
    o.x += a.x * inv;
    o.y += a.y * inv;
    o.z += a.z * inv;
    o.w += a.w * inv;
    ((float4*)out)[idx] = o;
    // re-zero scratch for next invocation
    ((float4*)g_acc)[aidx] = make_float4(0.f, 0.f, 0.f, 0.f);
    if (j == 0)
        g_den[hd * N + n] = 0.f;
}

// ------------------------------------------------------------------
extern "C" void kernel_launch(void* const* d_in, const int* in_sizes, int n_in,
                              void* d_out, int out_size)
{
    const float* x       = (const float*)d_in[0];
    const float* W_embed = (const float*)d_in[1];
    const float* a_src   = (const float*)d_in[2];
    const float* a_dst   = (const float*)d_in[3];
    const float* W_lin   = (const float*)d_in[4];
    const float* bias    = (const float*)d_in[5];
    const int*   src     = (const int*)d_in[6];
    const int*   dst     = (const int*)d_in[7];
    float* out = (float*)d_out;

    int N = in_sizes[0] / DF;
    int E = in_sizes[6];

    // 0. presplit weights (tiny)
    wsplit_kernel<<<(2 * DF * DF + 255) / 256, 256>>>(W_embed, W_lin);

    // 1. bf16-split tensor dual GEMM: h -> g_h (head-major), lin+bias -> d_out
    dim3 ggrid((N + 127) / 128, 2);
    gemm_kernel<<<ggrid, 256>>>(x, bias, out, N);

    // 2. attention dots
    dot_kernel<<<(N + 7) / 8, 256>>>(a_src, a_dst, N);

    // 3. edge passes, one head at a time (L2-resident working set)
    int eblocks = (E + 255) / 256;   // 8 warps/block * 32 edges/warp
    for (int hd = 0; hd < HEADS; hd++)
        edge_head_kernel<<<eblocks, 256>>>(src, dst, E, N, hd);

    // 4. finalize + re-zero scratch (acc/den zero-invariant across calls)
    final_kernel<<<(N * 32 + 255) / 256, 256>>>(out, N);
}

// round 16
// speedup vs baseline: 1.8370x; 1.0130x over previous
#include <cuda_runtime.h>
#include <cuda_bf16.h>
#include <cstdint>

#define MAXN 170000
#define DF   128
#define HEADS 4
#define NEG_SLOPE 0.2f

// -------- scratch (device globals; no allocations allowed) --------
// HEAD-MAJOR layouts: g_h/g_acc = [head][node][32], g_ds/dd/den = [head][node]
// g_acc / g_den are zero at kernel_launch entry: zero-initialized at load,
// re-zeroed by final_kernel after consumption (invariant across graph replays).
__device__ __align__(16) float g_h[MAXN * DF];
__device__ __align__(16) float g_acc[MAXN * DF];
__device__ __align__(16) float g_ds[MAXN * HEADS];
__device__ __align__(16) float g_dd[MAXN * HEADS];
__device__ __align__(16) float g_den[MAXN * HEADS];
// presplit transposed weights: [m][n][k], m=0:W_embed, m=1:W_lin
__device__ __align__(16) __nv_bfloat16 g_Whi[2 * DF * DF];
__device__ __align__(16) __nv_bfloat16 g_Wlo[2 * DF * DF];

// ---------------- W split + transpose (once per call) -------------
__global__ void wsplit_kernel(const float* __restrict__ We,
                              const float* __restrict__ Wl) {
    int idx = blockIdx.x * blockDim.x + threadIdx.x;   // 0..32767
    if (idx >= 2 * DF * DF) return;
    int m = idx >> 14;
    int r = idx & (DF * DF - 1);
    int kk = r >> 7;
    int nn = r & 127;
    float w = (m ? Wl : We)[kk * DF + nn];
    __nv_bfloat16 hi = __float2bfloat16(w);
    g_Whi[m * DF * DF + nn * DF + kk] = hi;
    g_Wlo[m * DF * DF + nn * DF + kk] =
        __float2bfloat16(w - __bfloat162float(hi));
}

// ---------------- bf16-split tensor-core dual GEMM ----------------
// D = A_hi*B_hi + A_hi*B_lo + A_lo*B_hi  (fp32 accum) ~ fp32 accuracy.
// by==0: x @ W_embed -> g_h (HEAD-MAJOR) ; by==1: x @ W_lin (+bias) -> d_out
// 2-stage smem pipeline: LDG for chunk k+1 issued before compute of chunk k.
#define KSTR 40                 // padded k-stride in bf16 elems
#define STG  (128 * KSTR)       // one buffer: 5120 bf16 elems
#define GEMM_SMEM_BYTES (8 * STG * 2)   // 8 buffers (4 arrays x 2 stages)

__device__ __forceinline__ void mma_bf16(float* c, const uint32_t* a,
                                         const uint32_t* b) {
    asm volatile(
        "mma.sync.aligned.m16n8k16.row.col.f32.bf16.bf16.f32 "
        "{%0,%1,%2,%3}, {%4,%5,%6,%7}, {%8,%9}, {%0,%1,%2,%3};\n"
        : "+f"(c[0]), "+f"(c[1]), "+f"(c[2]), "+f"(c[3])
        : "r"(a[0]), "r"(a[1]), "r"(a[2]), "r"(a[3]), "r"(b[0]), "r"(b[1]));
}

__device__ __forceinline__ uint32_t pack2(__nv_bfloat16 a, __nv_bfloat16 b) {
    __nv_bfloat162 t;
    t.x = a; t.y = b;
    return *(uint32_t*)&t;
}

__global__ __launch_bounds__(256, 2)
void gemm_kernel(const float* __restrict__ x,
                 const float* __restrict__ bias,
                 float* __restrict__ lin_out,
                 int N)
{
    extern __shared__ __nv_bfloat16 sm[];
    // buffer layout: [AsHi s0|s1][AsLo s0|s1][BsHi s0|s1][BsLo s0|s1]

    int by = blockIdx.y;
    const __nv_bfloat16* Wh = g_Whi + by * DF * DF;
    const __nv_bfloat16* Wl = g_Wlo + by * DF * DF;

    int tid = threadIdx.x;
    int warp = tid >> 5;
    int lane = tid & 31;
    int g = lane >> 2;          // 0..7
    int t = lane & 3;           // 0..3
    int wr = warp >> 1;         // 0..3
    int wc = warp & 1;          // 0..1
    int rowBase = blockIdx.x * 128;

    float acc[2][8][4];
    #pragma unroll
    for (int mt = 0; mt < 2; mt++)
        #pragma unroll
        for (int nt = 0; nt < 8; nt++)
            #pragma unroll
            for (int k = 0; k < 4; k++) acc[mt][nt][k] = 0.f;

    int xrow = tid >> 1;                 // 0..127  (also B row)
    int xkq  = (tid & 1) * 16;           // 0 or 16 (also B k-quad)
    int grow = rowBase + xrow;

    float4 aReg[4];
    uint4  bReg[4];

    // ---- pipeline helpers (inlined twice via lambdas) ----
    auto loadG = [&](int kc) {
        #pragma unroll
        for (int j = 0; j < 4; j++) {
            aReg[j] = make_float4(0.f, 0.f, 0.f, 0.f);
            if (grow < N)
                aReg[j] = *(const float4*)&x[grow * DF + kc + xkq + j * 4];
        }
        int goff = xrow * DF + kc + xkq;
        bReg[0] = *(const uint4*)&Wh[goff];
        bReg[1] = *(const uint4*)&Wh[goff + 8];
        bReg[2] = *(const uint4*)&Wl[goff];
        bReg[3] = *(const uint4*)&Wl[goff + 8];
    };
    auto storeS = [&](int st) {
        __nv_bfloat16* AsHi = sm + st * STG;
        __nv_bfloat16* AsLo = sm + 2 * STG + st * STG;
        __nv_bfloat16* BsHi = sm + 4 * STG + st * STG;
        __nv_bfloat16* BsLo = sm + 6 * STG + st * STG;
        #pragma unroll
        for (int j = 0; j < 4; j++) {
            float4 v = aReg[j];
            int base = xrow * KSTR + xkq + j * 4;
            __nv_bfloat16 h0 = __float2bfloat16(v.x);
            __nv_bfloat16 h1 = __float2bfloat16(v.y);
            __nv_bfloat16 h2 = __float2bfloat16(v.z);
            __nv_bfloat16 h3 = __float2bfloat16(v.w);
            *(uint2*)&AsHi[base] = make_uint2(pack2(h0, h1), pack2(h2, h3));
            *(uint2*)&AsLo[base] = make_uint2(
                pack2(__float2bfloat16(v.x - __bfloat162float(h0)),
                      __float2bfloat16(v.y - __bfloat162float(h1))),
                pack2(__float2bfloat16(v.z - __bfloat162float(h2)),
                      __float2bfloat16(v.w - __bfloat162float(h3))));
        }
        int soff = xrow * KSTR + xkq;
        *(uint4*)&BsHi[soff]     = bReg[0];
        *(uint4*)&BsHi[soff + 8] = bReg[1];
        *(uint4*)&BsLo[soff]     = bReg[2];
        *(uint4*)&BsLo[soff + 8] = bReg[3];
    };
    auto compute = [&](int st) {
        const __nv_bfloat16* AsHi = sm + st * STG;
        const __nv_bfloat16* AsLo = sm + 2 * STG + st * STG;
        const __nv_bfloat16* BsHi = sm + 4 * STG + st * STG;
        const __nv_bfloat16* BsLo = sm + 6 * STG + st * STG;
        #pragma unroll
        for (int ks = 0; ks < 32; ks += 16) {
            uint32_t ah[2][4], al[2][4];
            #pragma unroll
            for (int mt = 0; mt < 2; mt++) {
                int m0 = wr * 32 + mt * 16;
                int r0 = (m0 + g) * KSTR + ks + 2 * t;
                int r1 = (m0 + g + 8) * KSTR + ks + 2 * t;
                ah[mt][0] = *(const uint32_t*)&AsHi[r0];
                ah[mt][1] = *(const uint32_t*)&AsHi[r1];
                ah[mt][2] = *(const uint32_t*)&AsHi[r0 + 8];
                ah[mt][3] = *(const uint32_t*)&AsHi[r1 + 8];
                al[mt][0] = *(const uint32_t*)&AsLo[r0];
                al[mt][1] = *(const uint32_t*)&AsLo[r1];
                al[mt][2] = *(const uint32_t*)&AsLo[r0 + 8];
                al[mt][3] = *(const uint32_t*)&AsLo[r1 + 8];
            }
            #pragma unroll
            for (int nt = 0; nt < 8; nt++) {
                int n0 = wc * 64 + nt * 8;
                int bidx = (n0 + g) * KSTR + ks + 2 * t;
                uint32_t bh[2], bl[2];
                bh[0] = *(const uint32_t*)&BsHi[bidx];
                bh[1] = *(const uint32_t*)&BsHi[bidx + 8];
                bl[0] = *(const uint32_t*)&BsLo[bidx];
                bl[1] = *(const uint32_t*)&BsLo[bidx + 8];
                #pragma unroll
                for (int mt = 0; mt < 2; mt++) {
                    mma_bf16(acc[mt][nt], ah[mt], bh);   // hi*hi
                    mma_bf16(acc[mt][nt], ah[mt], bl);   // hi*lo
                    mma_bf16(acc[mt][nt], al[mt], bh);   // lo*hi
                }
            }
        }
    };

    // ---- 2-stage pipeline over 4 k-chunks ----
    loadG(0);
    storeS(0);
    __syncthreads();
    int buf = 0;
    #pragma unroll
    for (int kt = 0; kt < 4; kt++) {
        if (kt < 3) loadG((kt + 1) * 32);   // LDG overlapped with compute
        compute(buf);
        if (kt < 3) {
            storeS(buf ^ 1);                // other buffer: no WAR hazard
            __syncthreads();
            buf ^= 1;
        }
    }

    // --- epilogue ---
    int N32 = N * 32;
    #pragma unroll
    for (int nt = 0; nt < 8; nt++) {
        int col = wc * 64 + nt * 8 + 2 * t;
        float b0 = 0.f, b1 = 0.f;
        if (by) { b0 = bias[col]; b1 = bias[col + 1]; }
        int hd = col >> 5;
        int ch = col & 31;
        #pragma unroll
        for (int mt = 0; mt < 2; mt++) {
            int r0 = rowBase + wr * 32 + mt * 16 + g;
            if (r0 < N) {
                float2 o = make_float2(acc[mt][nt][0] + b0, acc[mt][nt][1] + b1);
                if (by) *(float2*)&lin_out[r0 * DF + col] = o;
                else    *(float2*)&g_h[hd * N32 + r0 * 32 + ch] = o;
            }
            int r1 = r0 + 8;
            if (r1 < N) {
                float2 o = make_float2(acc[mt][nt][2] + b0, acc[mt][nt][3] + b1);
                if (by) *(float2*)&lin_out[r1 * DF + col] = o;
                else    *(float2*)&g_h[hd * N32 + r1 * 32 + ch] = o;
            }
        }
    }
}

// ---------------- per-node attention dots (head-major h) ----------
__global__ void dot_kernel(const float* __restrict__ a_src,
                           const float* __restrict__ a_dst,
                           int N)
{
    int n = (blockIdx.x * blockDim.x + threadIdx.x) >> 5;
    int lane = threadIdx.x & 31;
    if (n >= N) return;
    int hd = lane >> 3;
    int lg = lane & 7;

    float4 hv = *(const float4*)&g_h[hd * (N * 32) + n * 32 + lg * 4];
    float4 as = ((const float4*)a_src)[lane];
    float4 ad = ((const float4*)a_dst)[lane];

    float ps = hv.x * as.x + hv.y * as.y + hv.z * as.z + hv.w * as.w;
    float pd = hv.x * ad.x + hv.y * ad.y + hv.z * ad.z + hv.w * ad.w;

    ps += __shfl_xor_sync(0xffffffffu, ps, 1);
    ps += __shfl_xor_sync(0xffffffffu, ps, 2);
    ps += __shfl_xor_sync(0xffffffffu, ps, 4);
    pd += __shfl_xor_sync(0xffffffffu, pd, 1);
    pd += __shfl_xor_sync(0xffffffffu, pd, 2);
    pd += __shfl_xor_sync(0xffffffffu, pd, 4);

    if (lg == 0) {
        g_ds[hd * N + n] = ps;
        g_dd[hd * N + n] = pd;
    }
}

// ---------------- per-head edge pass ------------------------------
// 32 edges/warp, 2 batches of 4 buffered gathers (MLP=4, low regs).
// 8 lanes per edge: one 128B line per gather/red.
__global__ __launch_bounds__(256, 6)
void edge_head_kernel(const int* __restrict__ src,
                      const int* __restrict__ dst,
                      int E, int N, int hd)
{
    int warpId = (blockIdx.x * blockDim.x + threadIdx.x) >> 5;
    int lane = threadIdx.x & 31;
    int base = warpId * 32;
    if (base >= E) return;
    int sub = lane >> 3;
    int lg  = lane & 7;

    // every lane computes scalars for edge base+lane
    int eL = base + lane;
    int sL = 0, dL = 0;
    float wL = 0.f;
    if (eL < E) {
        sL = __ldg(&src[eL]);
        dL = __ldg(&dst[eL]);
        float z = __ldg(&g_ds[hd * N + sL]) + __ldg(&g_dd[hd * N + dL]);
        z = (z >= 0.f) ? z : NEG_SLOPE * z;
        wL = __expf(z);
    }

    int N32 = N * 32;
    #pragma unroll
    for (int half = 0; half < 2; half++) {
        float4 v[4];
        int   dd[4];
        float ww[4];
        bool  act[4];
        #pragma unroll
        for (int it = 0; it < 4; it++) {
            int ln = half * 16 + it * 4 + sub;
            int e = base + ln;
            act[it] = (e < E);
            int s  = __shfl_sync(0xffffffffu, sL, ln);
            dd[it] = __shfl_sync(0xffffffffu, dL, ln);
            ww[it] = __shfl_sync(0xffffffffu, wL, ln);
            v[it] = make_float4(0.f, 0.f, 0.f, 0.f);
            if (act[it])
                v[it] = *(const float4*)&g_h[hd * N32 + s * 32 + lg * 4];
        }
        #pragma unroll
        for (int it = 0; it < 4; it++) {
            if (act[it]) {
                float w = ww[it];
                int d = dd[it];
                if (lg == 0)
                    atomicAdd(&g_den[hd * N + d], w);
                float a0 = w * v[it].x, a1 = w * v[it].y;
                float a2 = w * v[it].z, a3 = w * v[it].w;
                float* p = &g_acc[hd * N32 + d * 32 + lg * 4];
                asm volatile("red.global.add.v4.f32 [%0], {%1, %2, %3, %4};"
                             :: "l"(p), "f"(a0), "f"(a1), "f"(a2), "f"(a3)
                             : "memory");
            }
        }
    }
}

// ---------------- finalize + scratch re-zero ----------------------
__global__ void final_kernel(float* __restrict__ out, int N)
{
    int idx = blockIdx.x * blockDim.x + threadIdx.x;   // float4 index over N*32
    if (idx >= N * 32) return;
    int n = idx >> 5;
    int q = idx & 31;
    int hd = q >> 3;
    int j  = q & 7;
    float den = g_den[hd * N + n];
    float inv = (den > 0.f) ? (1.0f / den) : 0.f;
    int aidx = hd * (N * 8) + n * 8 + j;
    float4 a = ((const float4*)g_acc)[aidx];
    float4 o = ((float4*)out)[idx];
    o.x += a.x * inv;
    o.y += a.y * inv;
    o.z += a.z * inv;
    o.w += a.w * inv;
    ((float4*)out)[idx] = o;
    // re-zero scratch for next invocation
    ((float4*)g_acc)[aidx] = make_float4(0.f, 0.f, 0.f, 0.f);
    if (j == 0)
        g_den[hd * N + n] = 0.f;
}

// ------------------------------------------------------------------
extern "C" void kernel_launch(void* const* d_in, const int* in_sizes, int n_in,
                              void* d_out, int out_size)
{
    const float* x       = (const float*)d_in[0];
    const float* W_embed = (const float*)d_in[1];
    const float* a_src   = (const float*)d_in[2];
    const float* a_dst   = (const float*)d_in[3];
    const float* W_lin   = (const float*)d_in[4];
    const float* bias    = (const float*)d_in[5];
    const int*   src     = (const int*)d_in[6];
    const int*   dst     = (const int*)d_in[7];
    float* out = (float*)d_out;

    int N = in_sizes[0] / DF;
    int E = in_sizes[6];

    // raise dynamic smem cap for the pipelined GEMM (idempotent, no alloc)
    cudaFuncSetAttribute(gemm_kernel,
                         cudaFuncAttributeMaxDynamicSharedMemorySize,
                         GEMM_SMEM_BYTES);

    // 0. presplit weights (tiny)
    wsplit_kernel<<<(2 * DF * DF + 255) / 256, 256>>>(W_embed, W_lin);

    // 1. bf16-split tensor dual GEMM (2-stage pipelined)
    dim3 ggrid((N + 127) / 128, 2);
    gemm_kernel<<<ggrid, 256, GEMM_SMEM_BYTES>>>(x, bias, out, N);

    // 2. attention dots
    dot_kernel<<<(N + 7) / 8, 256>>>(a_src, a_dst, N);

    // 3. edge passes, one head at a time (L2-resident working set)
    int eblocks = (E + 255) / 256;   // 8 warps/block * 32 edges/warp
    for (int hd = 0; hd < HEADS; hd++)
        edge_head_kernel<<<eblocks, 256>>>(src, dst, E, N, hd);

    // 4. finalize + re-zero scratch (acc/den zero-invariant across calls)
    final_kernel<<<(N * 32 + 255) / 256, 256>>>(out, N);
}

// round 17
// speedup vs baseline: 1.8961x; 1.0322x over previous
#include <cuda_runtime.h>
#include <cuda_bf16.h>
#include <cstdint>

#define MAXN 170000
#define DF   128
#define HEADS 4
#define NEG_SLOPE 0.2f

// -------- scratch (device globals; no allocations allowed) --------
// HEAD-MAJOR layouts: g_h/g_acc = [head][node][32], g_ds/dd/den = [head][node]
// g_acc / g_den are zero at kernel_launch entry: zero-initialized at load,
// re-zeroed by final_kernel after consumption (invariant across graph replays).
__device__ __align__(16) float g_h[MAXN * DF];
__device__ __align__(16) float g_acc[MAXN * DF];
__device__ __align__(16) float g_ds[MAXN * HEADS];
__device__ __align__(16) float g_dd[MAXN * HEADS];
__device__ __align__(16) float g_den[MAXN * HEADS];
// presplit transposed weights: [m][n][k], m=0:W_embed, m=1:W_lin
__device__ __align__(16) __nv_bfloat16 g_Whi[2 * DF * DF];
__device__ __align__(16) __nv_bfloat16 g_Wlo[2 * DF * DF];

// ---------------- W split + transpose (once per call) -------------
__global__ void wsplit_kernel(const float* __restrict__ We,
                              const float* __restrict__ Wl) {
    int idx = blockIdx.x * blockDim.x + threadIdx.x;   // 0..32767
    if (idx >= 2 * DF * DF) return;
    int m = idx >> 14;
    int r = idx & (DF * DF - 1);
    int kk = r >> 7;
    int nn = r & 127;
    float w = (m ? Wl : We)[kk * DF + nn];
    __nv_bfloat16 hi = __float2bfloat16(w);
    g_Whi[m * DF * DF + nn * DF + kk] = hi;
    g_Wlo[m * DF * DF + nn * DF + kk] =
        __float2bfloat16(w - __bfloat162float(hi));
}

// ---------------- bf16-split tensor-core dual GEMM ----------------
// D = A_hi*B_hi + A_hi*B_lo + A_lo*B_hi  (fp32 accum) ~ fp32 accuracy.
// by==0: x @ W_embed -> g_h (HEAD-MAJOR) + fused attention dots -> g_ds/g_dd
// by==1: x @ W_lin (+bias) -> d_out
#define KSTR 40                 // padded k-stride in bf16 elems
#define STG  (128 * KSTR)       // one buffer: 5120 bf16 elems
#define GEMM_SMEM_BYTES (8 * STG * 2)   // 8 buffers (4 arrays x 2 stages)

__device__ __forceinline__ void mma_bf16(float* c, const uint32_t* a,
                                         const uint32_t* b) {
    asm volatile(
        "mma.sync.aligned.m16n8k16.row.col.f32.bf16.bf16.f32 "
        "{%0,%1,%2,%3}, {%4,%5,%6,%7}, {%8,%9}, {%0,%1,%2,%3};\n"
        : "+f"(c[0]), "+f"(c[1]), "+f"(c[2]), "+f"(c[3])
        : "r"(a[0]), "r"(a[1]), "r"(a[2]), "r"(a[3]), "r"(b[0]), "r"(b[1]));
}

__device__ __forceinline__ uint32_t pack2(__nv_bfloat16 a, __nv_bfloat16 b) {
    __nv_bfloat162 t;
    t.x = a; t.y = b;
    return *(uint32_t*)&t;
}

__global__ __launch_bounds__(256, 2)
void gemm_kernel(const float* __restrict__ x,
                 const float* __restrict__ bias,
                 const float* __restrict__ a_src,
                 const float* __restrict__ a_dst,
                 float* __restrict__ lin_out,
                 int N)
{
    extern __shared__ __nv_bfloat16 sm[];
    // buffer layout: [AsHi s0|s1][AsLo s0|s1][BsHi s0|s1][BsLo s0|s1]

    int by = blockIdx.y;
    const __nv_bfloat16* Wh = g_Whi + by * DF * DF;
    const __nv_bfloat16* Wl = g_Wlo + by * DF * DF;

    int tid = threadIdx.x;
    int warp = tid >> 5;
    int lane = tid & 31;
    int g = lane >> 2;          // 0..7
    int t = lane & 3;           // 0..3
    int wr = warp >> 1;         // 0..3
    int wc = warp & 1;          // 0..1
    int rowBase = blockIdx.x * 128;

    float acc[2][8][4];
    #pragma unroll
    for (int mt = 0; mt < 2; mt++)
        #pragma unroll
        for (int nt = 0; nt < 8; nt++)
            #pragma unroll
            for (int k = 0; k < 4; k++) acc[mt][nt][k] = 0.f;

    int xrow = tid >> 1;                 // 0..127  (also B row)
    int xkq  = (tid & 1) * 16;           // 0 or 16 (also B k-quad)
    int grow = rowBase + xrow;

    float4 aReg[4];
    uint4  bReg[4];

    auto loadG = [&](int kc) {
        #pragma unroll
        for (int j = 0; j < 4; j++) {
            aReg[j] = make_float4(0.f, 0.f, 0.f, 0.f);
            if (grow < N)
                aReg[j] = *(const float4*)&x[grow * DF + kc + xkq + j * 4];
        }
        int goff = xrow * DF + kc + xkq;
        bReg[0] = *(const uint4*)&Wh[goff];
        bReg[1] = *(const uint4*)&Wh[goff + 8];
        bReg[2] = *(const uint4*)&Wl[goff];
        bReg[3] = *(const uint4*)&Wl[goff + 8];
    };
    auto storeS = [&](int st) {
        __nv_bfloat16* AsHi = sm + st * STG;
        __nv_bfloat16* AsLo = sm + 2 * STG + st * STG;
        __nv_bfloat16* BsHi = sm + 4 * STG + st * STG;
        __nv_bfloat16* BsLo = sm + 6 * STG + st * STG;
        #pragma unroll
        for (int j = 0; j < 4; j++) {
            float4 v = aReg[j];
            int base = xrow * KSTR + xkq + j * 4;
            __nv_bfloat16 h0 = __float2bfloat16(v.x);
            __nv_bfloat16 h1 = __float2bfloat16(v.y);
            __nv_bfloat16 h2 = __float2bfloat16(v.z);
            __nv_bfloat16 h3 = __float2bfloat16(v.w);
            *(uint2*)&AsHi[base] = make_uint2(pack2(h0, h1), pack2(h2, h3));
            *(uint2*)&AsLo[base] = make_uint2(
                pack2(__float2bfloat16(v.x - __bfloat162float(h0)),
                      __float2bfloat16(v.y - __bfloat162float(h1))),
                pack2(__float2bfloat16(v.z - __bfloat162float(h2)),
                      __float2bfloat16(v.w - __bfloat162float(h3))));
        }
        int soff = xrow * KSTR + xkq;
        *(uint4*)&BsHi[soff]     = bReg[0];
        *(uint4*)&BsHi[soff + 8] = bReg[1];
        *(uint4*)&BsLo[soff]     = bReg[2];
        *(uint4*)&BsLo[soff + 8] = bReg[3];
    };
    auto compute = [&](int st) {
        const __nv_bfloat16* AsHi = sm + st * STG;
        const __nv_bfloat16* AsLo = sm + 2 * STG + st * STG;
        const __nv_bfloat16* BsHi = sm + 4 * STG + st * STG;
        const __nv_bfloat16* BsLo = sm + 6 * STG + st * STG;
        #pragma unroll
        for (int ks = 0; ks < 32; ks += 16) {
            uint32_t ah[2][4], al[2][4];
            #pragma unroll
            for (int mt = 0; mt < 2; mt++) {
                int m0 = wr * 32 + mt * 16;
                int r0 = (m0 + g) * KSTR + ks + 2 * t;
                int r1 = (m0 + g + 8) * KSTR + ks + 2 * t;
                ah[mt][0] = *(const uint32_t*)&AsHi[r0];
                ah[mt][1] = *(const uint32_t*)&AsHi[r1];
                ah[mt][2] = *(const uint32_t*)&AsHi[r0 + 8];
                ah[mt][3] = *(const uint32_t*)&AsHi[r1 + 8];
                al[mt][0] = *(const uint32_t*)&AsLo[r0];
                al[mt][1] = *(const uint32_t*)&AsLo[r1];
                al[mt][2] = *(const uint32_t*)&AsLo[r0 + 8];
                al[mt][3] = *(const uint32_t*)&AsLo[r1 + 8];
            }
            #pragma unroll
            for (int nt = 0; nt < 8; nt++) {
                int n0 = wc * 64 + nt * 8;
                int bidx = (n0 + g) * KSTR + ks + 2 * t;
                uint32_t bh[2], bl[2];
                bh[0] = *(const uint32_t*)&BsHi[bidx];
                bh[1] = *(const uint32_t*)&BsHi[bidx + 8];
                bl[0] = *(const uint32_t*)&BsLo[bidx];
                bl[1] = *(const uint32_t*)&BsLo[bidx + 8];
                #pragma unroll
                for (int mt = 0; mt < 2; mt++) {
                    mma_bf16(acc[mt][nt], ah[mt], bh);   // hi*hi
                    mma_bf16(acc[mt][nt], ah[mt], bl);   // hi*lo
                    mma_bf16(acc[mt][nt], al[mt], bh);   // lo*hi
                }
            }
        }
    };

    // ---- 2-stage pipeline over 4 k-chunks ----
    loadG(0);
    storeS(0);
    __syncthreads();
    int buf = 0;
    #pragma unroll
    for (int kt = 0; kt < 4; kt++) {
        if (kt < 3) loadG((kt + 1) * 32);
        compute(buf);
        if (kt < 3) {
            storeS(buf ^ 1);
            __syncthreads();
            buf ^= 1;
        }
    }

    // --- epilogue: store tiles ---
    int N32 = N * 32;
    #pragma unroll
    for (int nt = 0; nt < 8; nt++) {
        int col = wc * 64 + nt * 8 + 2 * t;
        float b0 = 0.f, b1 = 0.f;
        if (by) { b0 = bias[col]; b1 = bias[col + 1]; }
        int hd = col >> 5;
        int ch = col & 31;
        #pragma unroll
        for (int mt = 0; mt < 2; mt++) {
            int r0 = rowBase + wr * 32 + mt * 16 + g;
            if (r0 < N) {
                float2 o = make_float2(acc[mt][nt][0] + b0, acc[mt][nt][1] + b1);
                if (by) *(float2*)&lin_out[r0 * DF + col] = o;
                else    *(float2*)&g_h[hd * N32 + r0 * 32 + ch] = o;
            }
            int r1 = r0 + 8;
            if (r1 < N) {
                float2 o = make_float2(acc[mt][nt][2] + b0, acc[mt][nt][3] + b1);
                if (by) *(float2*)&lin_out[r1 * DF + col] = o;
                else    *(float2*)&g_h[hd * N32 + r1 * 32 + ch] = o;
            }
        }
    }

    // --- fused attention dots (by==0 only) ---
    // Thread holds h[r][col..col+1] for its 16 cols; a head's 32 cols live
    // entirely in this warp's wc half -> per-(row,head) dot completes with a
    // 4-lane (t) shfl reduction. Plain stores, each (row,head) written once.
    if (by == 0) {
        float ds0[2][2] = {{0.f, 0.f}, {0.f, 0.f}};   // [mt][h_idx] row r0
        float ds1[2][2] = {{0.f, 0.f}, {0.f, 0.f}};   // row r1
        float dd0[2][2] = {{0.f, 0.f}, {0.f, 0.f}};
        float dd1[2][2] = {{0.f, 0.f}, {0.f, 0.f}};
        #pragma unroll
        for (int nt = 0; nt < 8; nt++) {
            int h_idx = nt >> 2;
            int col = wc * 64 + nt * 8 + 2 * t;
            float a0 = __ldg(&a_src[col]);
            float a1 = __ldg(&a_src[col + 1]);
            float c0 = __ldg(&a_dst[col]);
            float c1 = __ldg(&a_dst[col + 1]);
            #pragma unroll
            for (int mt = 0; mt < 2; mt++) {
                ds0[mt][h_idx] += acc[mt][nt][0] * a0 + acc[mt][nt][1] * a1;
                ds1[mt][h_idx] += acc[mt][nt][2] * a0 + acc[mt][nt][3] * a1;
                dd0[mt][h_idx] += acc[mt][nt][0] * c0 + acc[mt][nt][1] * c1;
                dd1[mt][h_idx] += acc[mt][nt][2] * c0 + acc[mt][nt][3] * c1;
            }
        }
        #pragma unroll
        for (int mt = 0; mt < 2; mt++) {
            #pragma unroll
            for (int h_idx = 0; h_idx < 2; h_idx++) {
                float v0 = ds0[mt][h_idx], v1 = ds1[mt][h_idx];
                float w0 = dd0[mt][h_idx], w1 = dd1[mt][h_idx];
                v0 += __shfl_xor_sync(0xffffffffu, v0, 1);
                v0 += __shfl_xor_sync(0xffffffffu, v0, 2);
                v1 += __shfl_xor_sync(0xffffffffu, v1, 1);
                v1 += __shfl_xor_sync(0xffffffffu, v1, 2);
                w0 += __shfl_xor_sync(0xffffffffu, w0, 1);
                w0 += __shfl_xor_sync(0xffffffffu, w0, 2);
                w1 += __shfl_xor_sync(0xffffffffu, w1, 1);
                w1 += __shfl_xor_sync(0xffffffffu, w1, 2);
                if (t == 0) {
                    int head = wc * 2 + h_idx;
                    int r0 = rowBase + wr * 32 + mt * 16 + g;
                    int r1 = r0 + 8;
                    if (r0 < N) {
                        g_ds[head * N + r0] = v0;
                        g_dd[head * N + r0] = w0;
                    }
                    if (r1 < N) {
                        g_ds[head * N + r1] = v1;
                        g_dd[head * N + r1] = w1;
                    }
                }
            }
        }
    }
}

// ---------------- per-head edge pass ------------------------------
// 32 edges/warp, 2 batches of 4 buffered gathers (MLP=4, low regs).
// 8 lanes per edge: one 128B line per gather/red. At the L2 cap.
__global__ __launch_bounds__(256, 6)
void edge_head_kernel(const int* __restrict__ src,
                      const int* __restrict__ dst,
                      int E, int N, int hd)
{
    int warpId = (blockIdx.x * blockDim.x + threadIdx.x) >> 5;
    int lane = threadIdx.x & 31;
    int base = warpId * 32;
    if (base >= E) return;
    int sub = lane >> 3;
    int lg  = lane & 7;

    // every lane computes scalars for edge base+lane
    int eL = base + lane;
    int sL = 0, dL = 0;
    float wL = 0.f;
    if (eL < E) {
        sL = __ldg(&src[eL]);
        dL = __ldg(&dst[eL]);
        float z = __ldg(&g_ds[hd * N + sL]) + __ldg(&g_dd[hd * N + dL]);
        z = (z >= 0.f) ? z : NEG_SLOPE * z;
        wL = __expf(z);
    }

    int N32 = N * 32;
    #pragma unroll
    for (int half = 0; half < 2; half++) {
        float4 v[4];
        int   dd[4];
        float ww[4];
        bool  act[4];
        #pragma unroll
        for (int it = 0; it < 4; it++) {
            int ln = half * 16 + it * 4 + sub;
            int e = base + ln;
            act[it] = (e < E);
            int s  = __shfl_sync(0xffffffffu, sL, ln);
            dd[it] = __shfl_sync(0xffffffffu, dL, ln);
            ww[it] = __shfl_sync(0xffffffffu, wL, ln);
            v[it] = make_float4(0.f, 0.f, 0.f, 0.f);
            if (act[it])
                v[it] = *(const float4*)&g_h[hd * N32 + s * 32 + lg * 4];
        }
        #pragma unroll
        for (int it = 0; it < 4; it++) {
            if (act[it]) {
                float w = ww[it];
                int d = dd[it];
                if (lg == 0)
                    atomicAdd(&g_den[hd * N + d], w);
                float a0 = w * v[it].x, a1 = w * v[it].y;
                float a2 = w * v[it].z, a3 = w * v[it].w;
                float* p = &g_acc[hd * N32 + d * 32 + lg * 4];
                asm volatile("red.global.add.v4.f32 [%0], {%1, %2, %3, %4};"
                             :: "l"(p), "f"(a0), "f"(a1), "f"(a2), "f"(a3)
                             : "memory");
            }
        }
    }
}

// ---------------- finalize + scratch re-zero ----------------------
__global__ void final_kernel(float* __restrict__ out, int N)
{
    int idx = blockIdx.x * blockDim.x + threadIdx.x;   // float4 index over N*32
    if (idx >= N * 32) return;
    int n = idx >> 5;
    int q = idx & 31;
    int hd = q >> 3;
    int j  = q & 7;
    float den = g_den[hd * N + n];
    float inv = (den > 0.f) ? (1.0f / den) : 0.f;
    int aidx = hd * (N * 8) + n * 8 + j;
    float4 a = ((const float4*)g_acc)[aidx];
    float4 o = ((float4*)out)[idx];
    o.x += a.x * inv;
    o.y += a.y * inv;
    o.z += a.z * inv;
    o.w += a.w * inv;
    ((float4*)out)[idx] = o;
    // re-zero scratch for next invocation
    ((float4*)g_acc)[aidx] = make_float4(0.f, 0.f, 0.f, 0.f);
    if (j == 0)
        g_den[hd * N + n] = 0.f;
}

// ------------------------------------------------------------------
extern "C" void kernel_launch(void* const* d_in, const int* in_sizes, int n_in,
                              void* d_out, int out_size)
{
    const float* x       = (const float*)d_in[0];
    const float* W_embed = (const float*)d_in[1];
    const float* a_src   = (const float*)d_in[2];
    const float* a_dst   = (const float*)d_in[3];
    const float* W_lin   = (const float*)d_in[4];
    const float* bias    = (const float*)d_in[5];
    const int*   src     = (const int*)d_in[6];
    const int*   dst     = (const int*)d_in[7];
    float* out = (float*)d_out;

    int N = in_sizes[0] / DF;
    int E = in_sizes[6];

    // raise dynamic smem cap for the pipelined GEMM (idempotent, no alloc)
    cudaFuncSetAttribute(gemm_kernel,
                         cudaFuncAttributeMaxDynamicSharedMemorySize,
                         GEMM_SMEM_BYTES);

    // 0. presplit weights (tiny)
    wsplit_kernel<<<(2 * DF * DF + 255) / 256, 256>>>(W_embed, W_lin);

    // 1. bf16-split tensor dual GEMM + fused attention dots
    dim3 ggrid((N + 127) / 128, 2);
    gemm_kernel<<<ggrid, 256, GEMM_SMEM_BYTES>>>(x, bias, a_src, a_dst, out, N);

    // 2. edge passes, one head at a time (L2-resident working set)
    int eblocks = (E + 255) / 256;   // 8 warps/block * 32 edges/warp
    for (int hd = 0; hd < HEADS; hd++)
        edge_head_kernel<<<eblocks, 256>>>(src, dst, E, N, hd);

    // 3. finalize + re-zero scratch (acc/den zero-invariant across calls)
    final_kernel<<<(N * 32 + 255) / 256, 256>>>(out, N);
}